// round 1
// baseline (speedup 1.0000x reference)
#include <cuda_runtime.h>
#include <math.h>

// Problem dims
#define SEQ    512
#define NHEAD  12
#define DHEAD  64
#define CDIM   768
#define BPDIM  32              // B*P = 8*4
#define MTOK   (BPDIM * SEQ)   // 16384 tokens
#define QSCALE 0.125f          // 64^-0.5

// Scratch (device globals: allocation-free per harness rules)
__device__ float g_q[(size_t)BPDIM * NHEAD * SEQ * DHEAD];  // [bp*H+h][n][hd], pre-scaled
__device__ float g_k[(size_t)BPDIM * NHEAD * SEQ * DHEAD];
__device__ float g_v[(size_t)BPDIM * NHEAD * SEQ * DHEAD];
__device__ float g_o[(size_t)MTOK * CDIM];                  // merged-head, token-major

// ---------------------------------------------------------------------------
// SGEMM (NT): C[m,d] = sum_k A[m,k] * B[d,k]. 128x128 tile, BK=8, 256 thr, 8x8/thr.
// MODE 0: A = x, B = W_qkv; epilogue scatters into g_q (scaled) / g_k / g_v.
// MODE 1: A = g_o, B = W_proj; epilogue adds bias, writes d_out.
// ---------------------------------------------------------------------------
template <int MODE>
__global__ __launch_bounds__(256, 2)
void sgemm_nt(const float* __restrict__ A, const float* __restrict__ Bm,
              float* __restrict__ Cout, const float* __restrict__ bias, int K)
{
    __shared__ float As[8][128];
    __shared__ float Bs[8][128];

    const int tid = threadIdx.x;
    const int tx = tid & 15, ty = tid >> 4;
    const int bm = blockIdx.y, bn = blockIdx.x;

    const float* Aeff = (MODE == 0) ? A : g_o;

    const int lrow = tid >> 1;
    const int lcol = (tid & 1) * 4;
    const float* Ag = Aeff + (size_t)(bm * 128 + lrow) * K + lcol;
    const float* Bg = Bm   + (size_t)(bn * 128 + lrow) * K + lcol;

    float acc[8][8];
#pragma unroll
    for (int i = 0; i < 8; i++)
#pragma unroll
        for (int j = 0; j < 8; j++) acc[i][j] = 0.f;

    for (int kt = 0; kt < K; kt += 8) {
        float4 av = *(const float4*)(Ag + kt);
        float4 bv = *(const float4*)(Bg + kt);
        __syncthreads();
        As[lcol + 0][lrow] = av.x; As[lcol + 1][lrow] = av.y;
        As[lcol + 2][lrow] = av.z; As[lcol + 3][lrow] = av.w;
        Bs[lcol + 0][lrow] = bv.x; Bs[lcol + 1][lrow] = bv.y;
        Bs[lcol + 2][lrow] = bv.z; Bs[lcol + 3][lrow] = bv.w;
        __syncthreads();
#pragma unroll
        for (int kk = 0; kk < 8; kk++) {
            float4 a0 = *(const float4*)&As[kk][ty * 4];
            float4 a1 = *(const float4*)&As[kk][64 + ty * 4];
            float4 b0 = *(const float4*)&Bs[kk][tx * 4];
            float4 b1 = *(const float4*)&Bs[kk][64 + tx * 4];
            float a[8] = {a0.x, a0.y, a0.z, a0.w, a1.x, a1.y, a1.z, a1.w};
            float b[8] = {b0.x, b0.y, b0.z, b0.w, b1.x, b1.y, b1.z, b1.w};
#pragma unroll
            for (int i = 0; i < 8; i++)
#pragma unroll
                for (int j = 0; j < 8; j++)
                    acc[i][j] = fmaf(a[i], b[j], acc[i][j]);
        }
    }

#pragma unroll
    for (int i = 0; i < 8; i++) {
        const int m = bm * 128 + ty * 4 + (i & 3) + ((i >> 2) * 64);
        if (MODE == 0) {
            const int bp = m >> 9;           // token / 512
            const int n  = m & (SEQ - 1);
#pragma unroll
            for (int j = 0; j < 8; j++) {
                const int d   = bn * 128 + tx * 4 + (j & 3) + ((j >> 2) * 64);
                const int s   = d / CDIM;           // 0=q 1=k 2=v (tile never straddles)
                const int rem = d - s * CDIM;
                const int h   = rem >> 6;
                const int hd  = rem & 63;
                const size_t idx = ((size_t)(bp * NHEAD + h) * SEQ + n) * DHEAD + hd;
                const float val = acc[i][j];
                if (s == 0)      g_q[idx] = val * QSCALE;
                else if (s == 1) g_k[idx] = val;
                else             g_v[idx] = val;
            }
        } else {
            float* crow = Cout + (size_t)m * CDIM;
#pragma unroll
            for (int j = 0; j < 8; j++) {
                const int d = bn * 128 + tx * 4 + (j & 3) + ((j >> 2) * 64);
                crow[d] = acc[i][j] + bias[d];
            }
        }
    }
}

// ---------------------------------------------------------------------------
// Attention: one block per (head, 64-query tile). Full 64x512 score row in
// SMEM (two-pass softmax, no online rescale). 256 threads, 4x4 micro-tiles.
// SMEM: S 64x513 + Q 64x65 + KV 64x65 = 164608 B.
// ---------------------------------------------------------------------------
#define ATTN_SMEM ((64 * 513 + 2 * 64 * 65) * 4)

__global__ __launch_bounds__(256, 1)
void attn_kernel()
{
    extern __shared__ float sm[];
    float* S  = sm;                   // [64][513]
    float* Qs = sm + 64 * 513;        // [64][65]
    float* KV = Qs + 64 * 65;         // [64][65] (K tile, reused for V tiles)

    const int bph = blockIdx.x;       // 0..383  (bp*12 + h)
    const int qt  = blockIdx.y;       // 0..7
    const size_t headoff = (size_t)bph * SEQ * DHEAD;
    const float* qptr = g_q + headoff + (size_t)qt * 64 * DHEAD;
    const float* kptr = g_k + headoff;
    const float* vptr = g_v + headoff;

    const int tid = threadIdx.x;
    const int tx = tid & 15, ty = tid >> 4;

    // Load Q tile (pre-scaled at QKV epilogue)
    for (int i = tid; i < 1024; i += 256) {
        const int row = i >> 4;
        const int c4  = (i & 15) << 2;
        float4 val = *(const float4*)(qptr + row * 64 + c4);
        Qs[row * 65 + c4 + 0] = val.x; Qs[row * 65 + c4 + 1] = val.y;
        Qs[row * 65 + c4 + 2] = val.z; Qs[row * 65 + c4 + 3] = val.w;
    }

    // S = Q @ K^T, tile over 8 key chunks of 64
    for (int kt = 0; kt < 8; kt++) {
        __syncthreads();  // protect KV reuse across iterations (Q load covered too)
        for (int i = tid; i < 1024; i += 256) {
            const int row = i >> 4;
            const int c4  = (i & 15) << 2;
            float4 val = *(const float4*)(kptr + (size_t)kt * 64 * 64 + row * 64 + c4);
            KV[row * 65 + c4 + 0] = val.x; KV[row * 65 + c4 + 1] = val.y;
            KV[row * 65 + c4 + 2] = val.z; KV[row * 65 + c4 + 3] = val.w;
        }
        __syncthreads();

        float acc[4][4] = {{0.f}};
#pragma unroll 8
        for (int kk = 0; kk < 64; kk++) {
            float qv[4], kv[4];
#pragma unroll
            for (int ii = 0; ii < 4; ii++) qv[ii] = Qs[(ty * 4 + ii) * 65 + kk];
#pragma unroll
            for (int jj = 0; jj < 4; jj++) kv[jj] = KV[(tx * 4 + jj) * 65 + kk];
#pragma unroll
            for (int ii = 0; ii < 4; ii++)
#pragma unroll
                for (int jj = 0; jj < 4; jj++)
                    acc[ii][jj] = fmaf(qv[ii], kv[jj], acc[ii][jj]);
        }
#pragma unroll
        for (int ii = 0; ii < 4; ii++)
#pragma unroll
            for (int jj = 0; jj < 4; jj++)
                S[(ty * 4 + ii) * 513 + kt * 64 + tx * 4 + jj] = acc[ii][jj];
    }
    __syncthreads();

    // Row softmax: 4 threads per row (shfl within 4-lane groups)
    {
        const int row = tid >> 2;
        const int l4  = tid & 3;
        float* srow = S + row * 513;
        float mx = -1e30f;
        for (int j = l4; j < 512; j += 4) mx = fmaxf(mx, srow[j]);
        mx = fmaxf(mx, __shfl_xor_sync(0xffffffffu, mx, 1));
        mx = fmaxf(mx, __shfl_xor_sync(0xffffffffu, mx, 2));
        float sum = 0.f;
        for (int j = l4; j < 512; j += 4) {
            float e = __expf(srow[j] - mx);
            srow[j] = e;
            sum += e;
        }
        sum += __shfl_xor_sync(0xffffffffu, sum, 1);
        sum += __shfl_xor_sync(0xffffffffu, sum, 2);
        const float inv = 1.0f / sum;
        for (int j = l4; j < 512; j += 4) srow[j] *= inv;
    }

    // O = P @ V, tile over 8 value chunks of 64
    float acc[4][4] = {{0.f}};
    for (int vt = 0; vt < 8; vt++) {
        __syncthreads();  // softmax done (vt=0) / prior reads of KV done (vt>0)
        for (int i = tid; i < 1024; i += 256) {
            const int row = i >> 4;
            const int c4  = (i & 15) << 2;
            float4 val = *(const float4*)(vptr + (size_t)vt * 64 * 64 + row * 64 + c4);
            KV[row * 65 + c4 + 0] = val.x; KV[row * 65 + c4 + 1] = val.y;
            KV[row * 65 + c4 + 2] = val.z; KV[row * 65 + c4 + 3] = val.w;
        }
        __syncthreads();
#pragma unroll 8
        for (int jj0 = 0; jj0 < 64; jj0++) {
            const int j = vt * 64 + jj0;
            float sv[4], vv[4];
#pragma unroll
            for (int ii = 0; ii < 4; ii++) sv[ii] = S[(ty * 4 + ii) * 513 + j];
#pragma unroll
            for (int dd = 0; dd < 4; dd++) vv[dd] = KV[jj0 * 65 + tx * 4 + dd];
#pragma unroll
            for (int ii = 0; ii < 4; ii++)
#pragma unroll
                for (int dd = 0; dd < 4; dd++)
                    acc[ii][dd] = fmaf(sv[ii], vv[dd], acc[ii][dd]);
        }
    }

    // Write merged-head token-major: g_o[(bp*512 + q)*768 + h*64 + hd]
    const int h  = bph % NHEAD;
    const int bp = bph / NHEAD;
    const size_t obase = ((size_t)bp * SEQ + qt * 64) * CDIM + h * DHEAD;
#pragma unroll
    for (int ii = 0; ii < 4; ii++) {
        const int r = ty * 4 + ii;
#pragma unroll
        for (int dd = 0; dd < 4; dd++)
            g_o[obase + (size_t)r * CDIM + tx * 4 + dd] = acc[ii][dd];
    }
}

// ---------------------------------------------------------------------------
extern "C" void kernel_launch(void* const* d_in, const int* in_sizes, int n_in,
                              void* d_out, int out_size)
{
    const float* x     = (const float*)d_in[0];  // (8,4,512,768)
    const float* Wqkv  = (const float*)d_in[1];  // (2304,768)
    const float* Wproj = (const float*)d_in[2];  // (768,768)
    const float* bproj = (const float*)d_in[3];  // (768,)
    float* out = (float*)d_out;

    cudaFuncSetAttribute(attn_kernel,
                         cudaFuncAttributeMaxDynamicSharedMemorySize, ATTN_SMEM);

    dim3 blk(256);
    // QKV projection: M=16384, N=2304, K=768 -> scatter to g_q/g_k/g_v
    sgemm_nt<0><<<dim3(2304 / 128, MTOK / 128), blk>>>(x, Wqkv, nullptr, nullptr, CDIM);
    // Attention: 384 heads x 8 query tiles
    attn_kernel<<<dim3(BPDIM * NHEAD, SEQ / 64), blk, ATTN_SMEM>>>();
    // Output projection: M=16384, N=768, K=768, + bias -> d_out
    sgemm_nt<1><<<dim3(CDIM / 128, MTOK / 128), blk>>>(nullptr, Wproj, out, bproj, CDIM);
}

// round 3
// speedup vs baseline: 1.3042x; 1.3042x over previous
#include <cuda_runtime.h>
#include <cuda_bf16.h>
#include <math.h>
#include <stdint.h>

// Problem dims
#define SEQ    512
#define NHEAD  12
#define DHEAD  64
#define CDIM   768
#define BPDIM  32              // B*P = 8*4
#define MTOK   (BPDIM * SEQ)   // 16384 tokens
#define QSCALE 0.125f          // 64^-0.5

// ---------------------------------------------------------------------------
// Device-global scratch (allocation-free per harness rules)
// ---------------------------------------------------------------------------
__device__ float g_q[(size_t)BPDIM * NHEAD * SEQ * DHEAD];  // head-major, pre-scaled
__device__ float g_k[(size_t)BPDIM * NHEAD * SEQ * DHEAD];
__device__ float g_v[(size_t)BPDIM * NHEAD * SEQ * DHEAD];
__device__ float g_o[(size_t)MTOK * CDIM];                  // merged-head token-major

// bf16 two-term splits (hi + lo)
__device__ __nv_bfloat16 g_xh[(size_t)MTOK * CDIM];
__device__ __nv_bfloat16 g_xl[(size_t)MTOK * CDIM];
__device__ __nv_bfloat16 g_oh[(size_t)MTOK * CDIM];
__device__ __nv_bfloat16 g_ol[(size_t)MTOK * CDIM];
__device__ __nv_bfloat16 g_wqh[(size_t)3 * CDIM * CDIM];
__device__ __nv_bfloat16 g_wql[(size_t)3 * CDIM * CDIM];
__device__ __nv_bfloat16 g_wph[(size_t)CDIM * CDIM];
__device__ __nv_bfloat16 g_wpl[(size_t)CDIM * CDIM];

// ---------------------------------------------------------------------------
// Base-ISA tensor helpers (mma.sync + ldmatrix — valid on sm_103 base target)
// ---------------------------------------------------------------------------
__device__ __forceinline__ uint32_t smem_u32(const void* p) {
    uint32_t a;
    asm("{ .reg .u64 t; cvta.to.shared.u64 t, %1; cvt.u32.u64 %0, t; }"
        : "=r"(a) : "l"(p));
    return a;
}

__device__ __forceinline__ void ldmx4(uint32_t* r, uint32_t addr) {
    asm volatile("ldmatrix.sync.aligned.m8n8.x4.shared.b16 {%0,%1,%2,%3}, [%4];"
                 : "=r"(r[0]), "=r"(r[1]), "=r"(r[2]), "=r"(r[3]) : "r"(addr));
}

__device__ __forceinline__ void mma_bf16(float* c, const uint32_t* a,
                                         uint32_t b0, uint32_t b1) {
    asm volatile(
        "mma.sync.aligned.m16n8k16.row.col.f32.bf16.bf16.f32 "
        "{%0,%1,%2,%3}, {%4,%5,%6,%7}, {%8,%9}, {%0,%1,%2,%3};"
        : "+f"(c[0]), "+f"(c[1]), "+f"(c[2]), "+f"(c[3])
        : "r"(a[0]), "r"(a[1]), "r"(a[2]), "r"(a[3]), "r"(b0), "r"(b1));
}

// ---------------------------------------------------------------------------
// bf16 split kernel: hi = bf16(x), lo = bf16(x - hi)
// sel: 0=x  1=Wqkv  2=Wproj  3=g_o
// ---------------------------------------------------------------------------
__global__ void split_bf16(const float* __restrict__ in, int sel, int n4)
{
    __nv_bfloat16 *hi, *lo;
    if (sel == 0)      { hi = g_xh;  lo = g_xl; }
    else if (sel == 1) { hi = g_wqh; lo = g_wql; }
    else if (sel == 2) { hi = g_wph; lo = g_wpl; }
    else               { hi = g_oh;  lo = g_ol; in = g_o; }

    int i = blockIdx.x * blockDim.x + threadIdx.x;
    if (i >= n4) return;
    float4 v = ((const float4*)in)[i];
    __nv_bfloat16 h0 = __float2bfloat16_rn(v.x);
    __nv_bfloat16 h1 = __float2bfloat16_rn(v.y);
    __nv_bfloat16 h2 = __float2bfloat16_rn(v.z);
    __nv_bfloat16 h3 = __float2bfloat16_rn(v.w);
    __nv_bfloat16 l0 = __float2bfloat16_rn(v.x - __bfloat162float(h0));
    __nv_bfloat16 l1 = __float2bfloat16_rn(v.y - __bfloat162float(h1));
    __nv_bfloat16 l2 = __float2bfloat16_rn(v.z - __bfloat162float(h2));
    __nv_bfloat16 l3 = __float2bfloat16_rn(v.w - __bfloat162float(h3));
    ((__nv_bfloat162*)hi)[2 * i]     = __nv_bfloat162(h0, h1);
    ((__nv_bfloat162*)hi)[2 * i + 1] = __nv_bfloat162(h2, h3);
    ((__nv_bfloat162*)lo)[2 * i]     = __nv_bfloat162(l0, l1);
    ((__nv_bfloat162*)lo)[2 * i + 1] = __nv_bfloat162(l2, l3);
}

// ---------------------------------------------------------------------------
// Tensor-core GEMM (NT): C[m,d] = sum_k A[m,k]*B[d,k].
// bf16 split, 3 mma products, fp32 accumulate. CTA 128x128, BK=32, 8 warps
// (warp tile 64x32), double-buffered padded SMEM, LDG->reg prefetch.
// SMEM tile layout (bf16): [128 rows][40 cols] (80B rows, 16B-aligned).
// Buffers: {Ah, Al, Bh, Bl} x 10240B = 40960B per stage, x2 = 81920B.
// MODE 0: A=x split, B=Wqkv split; scatter to g_q (scaled)/g_k/g_v.
// MODE 1: A=g_o split, B=Wproj split; +bias -> d_out.
// ---------------------------------------------------------------------------
#define TILE_B   10240
#define STAGE_B  40960
#define GSMEM    (2 * STAGE_B)
#define NCHUNK   (CDIM / 32)   // 24

template <int MODE>
__global__ __launch_bounds__(256)
void gemm_tc(float* __restrict__ Cout, const float* __restrict__ bias)
{
    extern __shared__ char smem[];
    const uint32_t sb = smem_u32(smem);
    const int tid = threadIdx.x;
    const int l   = tid & 31;
    const int warp = tid >> 5;
    const int wm = warp & 1;        // 2 m-warps (64 rows each)
    const int wn = warp >> 1;       // 4 n-warps (32 cols each)
    const int bn = blockIdx.x, bm = blockIdx.y;
    const int K = CDIM;

    const __nv_bfloat16* pAh = (MODE == 0) ? g_xh : g_oh;
    const __nv_bfloat16* pAl = (MODE == 0) ? g_xl : g_ol;
    const __nv_bfloat16* pBh = (MODE == 0) ? g_wqh : g_wph;
    const __nv_bfloat16* pBl = (MODE == 0) ? g_wql : g_wpl;

    // Loader mapping: i in [0,2048): tile t=i>>9, row r=(i>>2)&127, seg u=i&3
    const __nv_bfloat16* srcs[4] = {
        pAh + (size_t)(bm * 128) * K, pAl + (size_t)(bm * 128) * K,
        pBh + (size_t)(bn * 128) * K, pBl + (size_t)(bn * 128) * K };

    // ldmatrix lane addressing pieces
    const int lrow   = l & 15;
    const int lcolb  = (l >> 4) << 4;   // 0 or 16 bytes

    float acc[4][4][4];
#pragma unroll
    for (int i = 0; i < 4; i++)
#pragma unroll
        for (int j = 0; j < 4; j++)
#pragma unroll
            for (int q = 0; q < 4; q++) acc[i][j][q] = 0.f;

    uint4 pf[8];

    // Prologue: load chunk 0 into stage 0
#pragma unroll
    for (int j = 0; j < 8; j++) {
        const int i = tid + j * 256;
        const int t = i >> 9, r = (i >> 2) & 127, u = i & 3;
        pf[j] = *(const uint4*)(srcs[t] + (size_t)r * K + u * 8);
    }
#pragma unroll
    for (int j = 0; j < 8; j++) {
        const int i = tid + j * 256;
        const int t = i >> 9, r = (i >> 2) & 127, u = i & 3;
        *(uint4*)(smem + t * TILE_B + r * 80 + u * 16) = pf[j];
    }
    __syncthreads();

    for (int c = 0; c < NCHUNK; c++) {
        const int cur = c & 1;
        // Prefetch next chunk into registers (overlaps with mma below)
        if (c + 1 < NCHUNK) {
#pragma unroll
            for (int j = 0; j < 8; j++) {
                const int i = tid + j * 256;
                const int t = i >> 9, r = (i >> 2) & 127, u = i & 3;
                pf[j] = *(const uint4*)(srcs[t] + (size_t)r * K + (c + 1) * 32 + u * 8);
            }
        }

        // Compute on current stage: 2 k16 steps
        const uint32_t stg = sb + cur * STAGE_B;
#pragma unroll
        for (int s = 0; s < 2; s++) {
            const int kb = s * 32 + lcolb;   // byte col within 80B row
            uint32_t bh[8], bl[8];
#pragma unroll
            for (int np = 0; np < 2; np++) {
                const int rowb = (wn * 32 + np * 16 + lrow) * 80 + kb;
                ldmx4(&bh[np * 4], stg + 2 * TILE_B + rowb);
                ldmx4(&bl[np * 4], stg + 3 * TILE_B + rowb);
            }
#pragma unroll
            for (int mt = 0; mt < 4; mt++) {
                const int rowb = (wm * 64 + mt * 16 + lrow) * 80 + kb;
                uint32_t ah[4], al[4];
                ldmx4(ah, stg + rowb);
                ldmx4(al, stg + TILE_B + rowb);
#pragma unroll
                for (int nt = 0; nt < 4; nt++) {
                    const int np = nt >> 1, q = nt & 1;
                    mma_bf16(acc[mt][nt], ah, bh[np * 4 + q], bh[np * 4 + q + 2]);
                    mma_bf16(acc[mt][nt], ah, bl[np * 4 + q], bl[np * 4 + q + 2]);
                    mma_bf16(acc[mt][nt], al, bh[np * 4 + q], bh[np * 4 + q + 2]);
                }
            }
        }
        __syncthreads();
        if (c + 1 < NCHUNK) {
            const uint32_t nstg = (c + 1) & 1;
#pragma unroll
            for (int j = 0; j < 8; j++) {
                const int i = tid + j * 256;
                const int t = i >> 9, r = (i >> 2) & 127, u = i & 3;
                *(uint4*)(smem + nstg * STAGE_B + t * TILE_B + r * 80 + u * 16) = pf[j];
            }
            __syncthreads();
        }
    }

    // Epilogue: C fragment thread layout: rows (l>>2), (l>>2)+8; cols 2*(l&3)
#pragma unroll
    for (int mt = 0; mt < 4; mt++) {
#pragma unroll
        for (int nt = 0; nt < 4; nt++) {
            const int m0 = bm * 128 + wm * 64 + mt * 16 + (l >> 2);
            const int d  = bn * 128 + wn * 32 + nt * 8 + 2 * (l & 3);
#pragma unroll
            for (int half = 0; half < 2; half++) {
                const int m = m0 + half * 8;
                const float v0 = acc[mt][nt][half * 2 + 0];
                const float v1 = acc[mt][nt][half * 2 + 1];
                if (MODE == 0) {
                    const int bp = m >> 9;
                    const int n  = m & (SEQ - 1);
                    const int ss  = d / CDIM;
                    const int rem = d - ss * CDIM;
                    const int h   = rem >> 6;
                    const int hd  = rem & 63;
                    float* dst = (ss == 0 ? g_q : (ss == 1 ? g_k : g_v))
                               + (((size_t)(bp * NHEAD + h) * SEQ + n) * DHEAD + hd);
                    const float sc = (ss == 0) ? QSCALE : 1.0f;
                    *(float2*)dst = make_float2(v0 * sc, v1 * sc);
                } else {
                    float2 bv = *(const float2*)(bias + d);
                    *(float2*)(Cout + (size_t)m * CDIM + d) =
                        make_float2(v0 + bv.x, v1 + bv.y);
                }
            }
        }
    }
}

// ---------------------------------------------------------------------------
// Attention (unchanged, known-correct): SIMT fp32, block per (head, 64-q tile)
// ---------------------------------------------------------------------------
#define ATTN_SMEM ((64 * 513 + 2 * 64 * 65) * 4)

__global__ __launch_bounds__(256, 1)
void attn_kernel()
{
    extern __shared__ float sm[];
    float* S  = sm;                   // [64][513]
    float* Qs = sm + 64 * 513;        // [64][65]
    float* KV = Qs + 64 * 65;         // [64][65]

    const int bph = blockIdx.x;
    const int qt  = blockIdx.y;
    const size_t headoff = (size_t)bph * SEQ * DHEAD;
    const float* qptr = g_q + headoff + (size_t)qt * 64 * DHEAD;
    const float* kptr = g_k + headoff;
    const float* vptr = g_v + headoff;

    const int tid = threadIdx.x;
    const int tx = tid & 15, ty = tid >> 4;

    for (int i = tid; i < 1024; i += 256) {
        const int row = i >> 4;
        const int c4  = (i & 15) << 2;
        float4 val = *(const float4*)(qptr + row * 64 + c4);
        Qs[row * 65 + c4 + 0] = val.x; Qs[row * 65 + c4 + 1] = val.y;
        Qs[row * 65 + c4 + 2] = val.z; Qs[row * 65 + c4 + 3] = val.w;
    }

    for (int kt = 0; kt < 8; kt++) {
        __syncthreads();
        for (int i = tid; i < 1024; i += 256) {
            const int row = i >> 4;
            const int c4  = (i & 15) << 2;
            float4 val = *(const float4*)(kptr + (size_t)kt * 64 * 64 + row * 64 + c4);
            KV[row * 65 + c4 + 0] = val.x; KV[row * 65 + c4 + 1] = val.y;
            KV[row * 65 + c4 + 2] = val.z; KV[row * 65 + c4 + 3] = val.w;
        }
        __syncthreads();

        float acc[4][4] = {{0.f}};
#pragma unroll 8
        for (int kk = 0; kk < 64; kk++) {
            float qv[4], kv[4];
#pragma unroll
            for (int ii = 0; ii < 4; ii++) qv[ii] = Qs[(ty * 4 + ii) * 65 + kk];
#pragma unroll
            for (int jj = 0; jj < 4; jj++) kv[jj] = KV[(tx * 4 + jj) * 65 + kk];
#pragma unroll
            for (int ii = 0; ii < 4; ii++)
#pragma unroll
                for (int jj = 0; jj < 4; jj++)
                    acc[ii][jj] = fmaf(qv[ii], kv[jj], acc[ii][jj]);
        }
#pragma unroll
        for (int ii = 0; ii < 4; ii++)
#pragma unroll
            for (int jj = 0; jj < 4; jj++)
                S[(ty * 4 + ii) * 513 + kt * 64 + tx * 4 + jj] = acc[ii][jj];
    }
    __syncthreads();

    {
        const int row = tid >> 2;
        const int l4  = tid & 3;
        float* srow = S + row * 513;
        float mx = -1e30f;
        for (int j = l4; j < 512; j += 4) mx = fmaxf(mx, srow[j]);
        mx = fmaxf(mx, __shfl_xor_sync(0xffffffffu, mx, 1));
        mx = fmaxf(mx, __shfl_xor_sync(0xffffffffu, mx, 2));
        float sum = 0.f;
        for (int j = l4; j < 512; j += 4) {
            float e = __expf(srow[j] - mx);
            srow[j] = e;
            sum += e;
        }
        sum += __shfl_xor_sync(0xffffffffu, sum, 1);
        sum += __shfl_xor_sync(0xffffffffu, sum, 2);
        const float inv = 1.0f / sum;
        for (int j = l4; j < 512; j += 4) srow[j] *= inv;
    }

    float acc[4][4] = {{0.f}};
    for (int vt = 0; vt < 8; vt++) {
        __syncthreads();
        for (int i = tid; i < 1024; i += 256) {
            const int row = i >> 4;
            const int c4  = (i & 15) << 2;
            float4 val = *(const float4*)(vptr + (size_t)vt * 64 * 64 + row * 64 + c4);
            KV[row * 65 + c4 + 0] = val.x; KV[row * 65 + c4 + 1] = val.y;
            KV[row * 65 + c4 + 2] = val.z; KV[row * 65 + c4 + 3] = val.w;
        }
        __syncthreads();
#pragma unroll 8
        for (int jj0 = 0; jj0 < 64; jj0++) {
            const int j = vt * 64 + jj0;
            float sv[4], vv[4];
#pragma unroll
            for (int ii = 0; ii < 4; ii++) sv[ii] = S[(ty * 4 + ii) * 513 + j];
#pragma unroll
            for (int dd = 0; dd < 4; dd++) vv[dd] = KV[jj0 * 65 + tx * 4 + dd];
#pragma unroll
            for (int ii = 0; ii < 4; ii++)
#pragma unroll
                for (int dd = 0; dd < 4; dd++)
                    acc[ii][dd] = fmaf(sv[ii], vv[dd], acc[ii][dd]);
        }
    }

    const int h  = bph % NHEAD;
    const int bp = bph / NHEAD;
    const size_t obase = ((size_t)bp * SEQ + qt * 64) * CDIM + h * DHEAD;
#pragma unroll
    for (int ii = 0; ii < 4; ii++) {
        const int r = ty * 4 + ii;
#pragma unroll
        for (int dd = 0; dd < 4; dd++)
            g_o[obase + (size_t)r * CDIM + tx * 4 + dd] = acc[ii][dd];
    }
}

// ---------------------------------------------------------------------------
extern "C" void kernel_launch(void* const* d_in, const int* in_sizes, int n_in,
                              void* d_out, int out_size)
{
    const float* x     = (const float*)d_in[0];  // (8,4,512,768)
    const float* Wqkv  = (const float*)d_in[1];  // (2304,768)
    const float* Wproj = (const float*)d_in[2];  // (768,768)
    const float* bproj = (const float*)d_in[3];  // (768,)
    float* out = (float*)d_out;

    cudaFuncSetAttribute(gemm_tc<0>, cudaFuncAttributeMaxDynamicSharedMemorySize, GSMEM);
    cudaFuncSetAttribute(gemm_tc<1>, cudaFuncAttributeMaxDynamicSharedMemorySize, GSMEM);
    cudaFuncSetAttribute(attn_kernel, cudaFuncAttributeMaxDynamicSharedMemorySize, ATTN_SMEM);

    const int nx4 = MTOK * CDIM / 4;
    const int nq4 = 3 * CDIM * CDIM / 4;
    const int np4 = CDIM * CDIM / 4;

    split_bf16<<<(nx4 + 255) / 256, 256>>>(x, 0, nx4);
    split_bf16<<<(nq4 + 255) / 256, 256>>>(Wqkv, 1, nq4);
    split_bf16<<<(np4 + 255) / 256, 256>>>(Wproj, 2, np4);

    // QKV projection: (16384 x 2304 x 768) on tensor cores
    gemm_tc<0><<<dim3(3 * CDIM / 128, MTOK / 128), 256, GSMEM>>>(nullptr, nullptr);

    // Attention (SIMT fp32)
    attn_kernel<<<dim3(BPDIM * NHEAD, SEQ / 64), 256, ATTN_SMEM>>>();

    // Output projection: (16384 x 768 x 768) + bias
    split_bf16<<<(nx4 + 255) / 256, 256>>>(nullptr, 3, nx4);
    gemm_tc<1><<<dim3(CDIM / 128, MTOK / 128), 256, GSMEM>>>(out, bproj);
}

// round 4
// speedup vs baseline: 2.2180x; 1.7006x over previous
#include <cuda_runtime.h>
#include <cuda_bf16.h>
#include <math.h>
#include <stdint.h>

// Problem dims
#define SEQ    512
#define NHEAD  12
#define DHEAD  64
#define CDIM   768
#define BPDIM  32              // B*P = 8*4
#define MTOK   (BPDIM * SEQ)   // 16384 tokens
#define QSCALE 0.125f          // 64^-0.5

// ---------------------------------------------------------------------------
// Device-global scratch (allocation-free per harness rules)
// ---------------------------------------------------------------------------
#define HELEMS ((size_t)BPDIM * NHEAD * SEQ * DHEAD)   // 12.58M

// q/k/v as bf16 two-term splits, head-major [bp*12+h][n][hd]; q pre-scaled
__device__ __nv_bfloat16 g_qh[HELEMS];
__device__ __nv_bfloat16 g_ql[HELEMS];
__device__ __nv_bfloat16 g_kh[HELEMS];
__device__ __nv_bfloat16 g_kl[HELEMS];
__device__ __nv_bfloat16 g_vh[HELEMS];
__device__ __nv_bfloat16 g_vl[HELEMS];

// bf16 two-term splits for GEMM inputs / attention output (token-major)
__device__ __nv_bfloat16 g_xh[(size_t)MTOK * CDIM];
__device__ __nv_bfloat16 g_xl[(size_t)MTOK * CDIM];
__device__ __nv_bfloat16 g_oh[(size_t)MTOK * CDIM];
__device__ __nv_bfloat16 g_ol[(size_t)MTOK * CDIM];
__device__ __nv_bfloat16 g_wqh[(size_t)3 * CDIM * CDIM];
__device__ __nv_bfloat16 g_wql[(size_t)3 * CDIM * CDIM];
__device__ __nv_bfloat16 g_wph[(size_t)CDIM * CDIM];
__device__ __nv_bfloat16 g_wpl[(size_t)CDIM * CDIM];

// ---------------------------------------------------------------------------
// Base-ISA tensor helpers (mma.sync + ldmatrix — valid on sm_103 base target)
// ---------------------------------------------------------------------------
__device__ __forceinline__ uint32_t smem_u32(const void* p) {
    uint32_t a;
    asm("{ .reg .u64 t; cvta.to.shared.u64 t, %1; cvt.u32.u64 %0, t; }"
        : "=r"(a) : "l"(p));
    return a;
}

__device__ __forceinline__ void ldmx4(uint32_t* r, uint32_t addr) {
    asm volatile("ldmatrix.sync.aligned.m8n8.x4.shared.b16 {%0,%1,%2,%3}, [%4];"
                 : "=r"(r[0]), "=r"(r[1]), "=r"(r[2]), "=r"(r[3]) : "r"(addr));
}
__device__ __forceinline__ void ldmx4t(uint32_t* r, uint32_t addr) {
    asm volatile("ldmatrix.sync.aligned.m8n8.x4.trans.shared.b16 {%0,%1,%2,%3}, [%4];"
                 : "=r"(r[0]), "=r"(r[1]), "=r"(r[2]), "=r"(r[3]) : "r"(addr));
}

__device__ __forceinline__ void mma_bf16(float* c, const uint32_t* a,
                                         uint32_t b0, uint32_t b1) {
    asm volatile(
        "mma.sync.aligned.m16n8k16.row.col.f32.bf16.bf16.f32 "
        "{%0,%1,%2,%3}, {%4,%5,%6,%7}, {%8,%9}, {%0,%1,%2,%3};"
        : "+f"(c[0]), "+f"(c[1]), "+f"(c[2]), "+f"(c[3])
        : "r"(a[0]), "r"(a[1]), "r"(a[2]), "r"(a[3]), "r"(b0), "r"(b1));
}

__device__ __forceinline__ void split2(float a0, float a1,
                                       uint32_t& hi, uint32_t& lo) {
    __nv_bfloat16 h0 = __float2bfloat16_rn(a0);
    __nv_bfloat16 h1 = __float2bfloat16_rn(a1);
    __nv_bfloat16 l0 = __float2bfloat16_rn(a0 - __bfloat162float(h0));
    __nv_bfloat16 l1 = __float2bfloat16_rn(a1 - __bfloat162float(h1));
    __nv_bfloat162 hh(h0, h1), ll(l0, l1);
    hi = *(uint32_t*)&hh;
    lo = *(uint32_t*)&ll;
}

// ---------------------------------------------------------------------------
// bf16 split kernel: hi = bf16(x), lo = bf16(x - hi).  sel: 0=x 1=Wqkv 2=Wproj
// ---------------------------------------------------------------------------
__global__ void split_bf16(const float* __restrict__ in, int sel, int n4)
{
    __nv_bfloat16 *hi, *lo;
    if (sel == 0)      { hi = g_xh;  lo = g_xl; }
    else if (sel == 1) { hi = g_wqh; lo = g_wql; }
    else               { hi = g_wph; lo = g_wpl; }

    int i = blockIdx.x * blockDim.x + threadIdx.x;
    if (i >= n4) return;
    float4 v = ((const float4*)in)[i];
    uint32_t h01, l01, h23, l23;
    split2(v.x, v.y, h01, l01);
    split2(v.z, v.w, h23, l23);
    ((uint32_t*)hi)[2 * i]     = h01;
    ((uint32_t*)hi)[2 * i + 1] = h23;
    ((uint32_t*)lo)[2 * i]     = l01;
    ((uint32_t*)lo)[2 * i + 1] = l23;
}

// ---------------------------------------------------------------------------
// Tensor-core GEMM (NT): C[m,d] = sum_k A[m,k]*B[d,k]. bf16 split, 3 products.
// CTA 128x128, BK=32, 8 warps (warp tile 64x32), double-buffered SMEM.
// MODE 0: A=x split, B=Wqkv split; epilogue splits+scatters to g_{q,k,v}{h,l}.
// MODE 1: A=g_o split, B=Wproj split; +bias -> d_out (fp32).
// ---------------------------------------------------------------------------
#define TILE_B   10240
#define STAGE_B  40960
#define GSMEM    (2 * STAGE_B)
#define NCHUNK   (CDIM / 32)   // 24

template <int MODE>
__global__ __launch_bounds__(256)
void gemm_tc(float* __restrict__ Cout, const float* __restrict__ bias)
{
    extern __shared__ char smem[];
    const uint32_t sb = smem_u32(smem);
    const int tid = threadIdx.x;
    const int l   = tid & 31;
    const int warp = tid >> 5;
    const int wm = warp & 1;
    const int wn = warp >> 1;
    const int bn = blockIdx.x, bm = blockIdx.y;
    const int K = CDIM;

    const __nv_bfloat16* pAh = (MODE == 0) ? g_xh : g_oh;
    const __nv_bfloat16* pAl = (MODE == 0) ? g_xl : g_ol;
    const __nv_bfloat16* pBh = (MODE == 0) ? g_wqh : g_wph;
    const __nv_bfloat16* pBl = (MODE == 0) ? g_wql : g_wpl;

    const __nv_bfloat16* srcs[4] = {
        pAh + (size_t)(bm * 128) * K, pAl + (size_t)(bm * 128) * K,
        pBh + (size_t)(bn * 128) * K, pBl + (size_t)(bn * 128) * K };

    const int lrow  = l & 15;
    const int lcolb = (l >> 4) << 4;

    float acc[4][4][4];
#pragma unroll
    for (int i = 0; i < 4; i++)
#pragma unroll
        for (int j = 0; j < 4; j++)
#pragma unroll
            for (int q = 0; q < 4; q++) acc[i][j][q] = 0.f;

    uint4 pf[8];
#pragma unroll
    for (int j = 0; j < 8; j++) {
        const int i = tid + j * 256;
        const int t = i >> 9, r = (i >> 2) & 127, u = i & 3;
        pf[j] = *(const uint4*)(srcs[t] + (size_t)r * K + u * 8);
    }
#pragma unroll
    for (int j = 0; j < 8; j++) {
        const int i = tid + j * 256;
        const int t = i >> 9, r = (i >> 2) & 127, u = i & 3;
        *(uint4*)(smem + t * TILE_B + r * 80 + u * 16) = pf[j];
    }
    __syncthreads();

    for (int c = 0; c < NCHUNK; c++) {
        const int cur = c & 1;
        if (c + 1 < NCHUNK) {
#pragma unroll
            for (int j = 0; j < 8; j++) {
                const int i = tid + j * 256;
                const int t = i >> 9, r = (i >> 2) & 127, u = i & 3;
                pf[j] = *(const uint4*)(srcs[t] + (size_t)r * K + (c + 1) * 32 + u * 8);
            }
        }

        const uint32_t stg = sb + cur * STAGE_B;
#pragma unroll
        for (int s = 0; s < 2; s++) {
            const int kb = s * 32 + lcolb;
            uint32_t bh[8], bl[8];
#pragma unroll
            for (int np = 0; np < 2; np++) {
                const int rowb = (wn * 32 + np * 16 + lrow) * 80 + kb;
                ldmx4(&bh[np * 4], stg + 2 * TILE_B + rowb);
                ldmx4(&bl[np * 4], stg + 3 * TILE_B + rowb);
            }
#pragma unroll
            for (int mt = 0; mt < 4; mt++) {
                const int rowb = (wm * 64 + mt * 16 + lrow) * 80 + kb;
                uint32_t ah[4], al[4];
                ldmx4(ah, stg + rowb);
                ldmx4(al, stg + TILE_B + rowb);
#pragma unroll
                for (int nt = 0; nt < 4; nt++) {
                    const int np = nt >> 1, q = nt & 1;
                    mma_bf16(acc[mt][nt], ah, bh[np * 4 + q], bh[np * 4 + q + 2]);
                    mma_bf16(acc[mt][nt], ah, bl[np * 4 + q], bl[np * 4 + q + 2]);
                    mma_bf16(acc[mt][nt], al, bh[np * 4 + q], bh[np * 4 + q + 2]);
                }
            }
        }
        __syncthreads();
        if (c + 1 < NCHUNK) {
            const uint32_t nstg = (c + 1) & 1;
#pragma unroll
            for (int j = 0; j < 8; j++) {
                const int i = tid + j * 256;
                const int t = i >> 9, r = (i >> 2) & 127, u = i & 3;
                *(uint4*)(smem + nstg * STAGE_B + t * TILE_B + r * 80 + u * 16) = pf[j];
            }
            __syncthreads();
        }
    }

#pragma unroll
    for (int mt = 0; mt < 4; mt++) {
#pragma unroll
        for (int nt = 0; nt < 4; nt++) {
            const int m0 = bm * 128 + wm * 64 + mt * 16 + (l >> 2);
            const int d  = bn * 128 + wn * 32 + nt * 8 + 2 * (l & 3);
#pragma unroll
            for (int half = 0; half < 2; half++) {
                const int m = m0 + half * 8;
                const float v0 = acc[mt][nt][half * 2 + 0];
                const float v1 = acc[mt][nt][half * 2 + 1];
                if (MODE == 0) {
                    const int bp = m >> 9;
                    const int n  = m & (SEQ - 1);
                    const int ss  = d / CDIM;
                    const int rem = d - ss * CDIM;
                    const int h   = rem >> 6;
                    const int hd  = rem & 63;
                    const size_t base = ((size_t)(bp * NHEAD + h) * SEQ + n) * DHEAD + hd;
                    const float sc = (ss == 0) ? QSCALE : 1.0f;
                    uint32_t hi, lo;
                    split2(v0 * sc, v1 * sc, hi, lo);
                    __nv_bfloat16* dh = (ss == 0) ? g_qh : (ss == 1) ? g_kh : g_vh;
                    __nv_bfloat16* dl = (ss == 0) ? g_ql : (ss == 1) ? g_kl : g_vl;
                    *(uint32_t*)(dh + base) = hi;
                    *(uint32_t*)(dl + base) = lo;
                } else {
                    float2 bv = *(const float2*)(bias + d);
                    *(float2*)(Cout + (size_t)m * CDIM + d) =
                        make_float2(v0 + bv.x, v1 + bv.y);
                }
            }
        }
    }
}

// ---------------------------------------------------------------------------
// Tensor-core attention: one block per (head, 64-query tile), 256 thr / 8 warps.
// Phase 1: S = Q·K^T (bf16 split, 3 products) -> SMEM fp32 [64][524].
// Phase 2: row softmax (store unnormalized e; inv folded into epilogue).
// Phase 3: O = e·V per 64-key chunk (convert e->bf16 split; ldmatrix.trans V).
// Epilogue: O*inv split -> g_oh/g_ol merged-head token-major.
// ---------------------------------------------------------------------------
#define AS_STRIDE 524
#define ATILE     9216                       // 64 rows * 144B
#define SM_Q      (64 * AS_STRIDE * 4)       // 134144: SQh, SQl
#define SM_KV     (SM_Q + 2 * ATILE)         // 152576: 2 bufs x {h,l}
#define SM_P      (SM_KV + 4 * ATILE)        // 189440: SPh, SPl
#define SM_INV    (SM_P + 2 * ATILE)         // 207872
#define ATTN_SMEM (SM_INV + 256)             // 208128

__global__ __launch_bounds__(256, 1)
void attn_tc()
{
    extern __shared__ char sm[];
    float* S = (float*)sm;
    float* sInv = (float*)(sm + SM_INV);
    const uint32_t sb = smem_u32(sm);
    const int tid = threadIdx.x, l = tid & 31, w = tid >> 5;
    const int mw = w & 3, nw = w >> 2;
    const int bph = blockIdx.x, qt = blockIdx.y;
    const size_t hoff = (size_t)bph * SEQ * DHEAD;
    const __nv_bfloat16* qh = g_qh + hoff + (size_t)qt * 64 * DHEAD;
    const __nv_bfloat16* ql = g_ql + hoff + (size_t)qt * 64 * DHEAD;
    const __nv_bfloat16* kh = g_kh + hoff;
    const __nv_bfloat16* kl = g_kl + hoff;
    const __nv_bfloat16* vh = g_vh + hoff;
    const __nv_bfloat16* vl = g_vl + hoff;

    const int lrow  = l & 15;
    const int lcolb = (l >> 4) << 4;

    // Prologue: Q tiles (h,l) + K chunk 0 (h,l): 4 tiles x 512 uint4
    for (int i = tid; i < 2048; i += 256) {
        const int t = i >> 9, r = (i >> 3) & 63, u = i & 7;
        const __nv_bfloat16* src = (t == 0) ? qh : (t == 1) ? ql : (t == 2) ? kh : kl;
        char* dst = sm + ((t < 2) ? (SM_Q + t * ATILE) : (SM_KV + (t - 2) * ATILE));
        *(uint4*)(dst + r * 144 + u * 16) = *(const uint4*)(src + r * 64 + u * 8);
    }
    __syncthreads();

    // Preload Q fragments (reused for all 8 key chunks)
    uint32_t qfh[4][4], qfl[4][4];
    {
        const uint32_t sqh = sb + SM_Q, sql = sqh + ATILE;
#pragma unroll
        for (int ks = 0; ks < 4; ks++) {
            const uint32_t ro = (mw * 16 + lrow) * 144 + ks * 32 + lcolb;
            ldmx4(qfh[ks], sqh + ro);
            ldmx4(qfl[ks], sql + ro);
        }
    }

    const uint32_t skv = sb + SM_KV;

    // ---- Phase 1: S = Q K^T ----
    for (int kc = 0; kc < 8; kc++) {
        uint4 pf[4];
        if (kc < 7) {
#pragma unroll
            for (int j = 0; j < 4; j++) {
                const int i = tid + j * 256;
                const int t = i >> 9, r = (i >> 3) & 63, u = i & 7;
                const __nv_bfloat16* src = ((t == 0) ? kh : kl) + (size_t)(kc + 1) * 64 * 64;
                pf[j] = *(const uint4*)(src + r * 64 + u * 8);
            }
        }
        const uint32_t cb = skv + (kc & 1) * 2 * ATILE;
        float accS[4][4] = {};
#pragma unroll
        for (int ks = 0; ks < 4; ks++) {
            uint32_t kbh[8], kbl[8];
#pragma unroll
            for (int np = 0; np < 2; np++) {
                const uint32_t ro = (nw * 32 + np * 16 + lrow) * 144 + ks * 32 + lcolb;
                ldmx4(&kbh[np * 4], cb + ro);
                ldmx4(&kbl[np * 4], cb + ATILE + ro);
            }
#pragma unroll
            for (int nt = 0; nt < 4; nt++) {
                const int np = nt >> 1, q = nt & 1;
                mma_bf16(accS[nt], qfh[ks], kbh[np * 4 + q], kbh[np * 4 + q + 2]);
                mma_bf16(accS[nt], qfh[ks], kbl[np * 4 + q], kbl[np * 4 + q + 2]);
                mma_bf16(accS[nt], qfl[ks], kbh[np * 4 + q], kbh[np * 4 + q + 2]);
            }
        }
#pragma unroll
        for (int nt = 0; nt < 4; nt++) {
            const int row = mw * 16 + (l >> 2);
            const int col = kc * 64 + nw * 32 + nt * 8 + 2 * (l & 3);
            *(float2*)&S[row * AS_STRIDE + col]       = make_float2(accS[nt][0], accS[nt][1]);
            *(float2*)&S[(row + 8) * AS_STRIDE + col] = make_float2(accS[nt][2], accS[nt][3]);
        }
        if (kc < 7) {
#pragma unroll
            for (int j = 0; j < 4; j++) {
                const int i = tid + j * 256;
                const int t = i >> 9, r = (i >> 3) & 63, u = i & 7;
                char* dst = sm + SM_KV + ((kc + 1) & 1) * 2 * ATILE + t * ATILE;
                *(uint4*)(dst + r * 144 + u * 16) = pf[j];
            }
        }
        __syncthreads();
    }

    // ---- Phase 2: V chunk-0 preload + softmax (unnormalized e kept in S) ----
    for (int i = tid; i < 1024; i += 256) {
        const int t = i >> 9, r = (i >> 3) & 63, u = i & 7;
        const __nv_bfloat16* src = (t == 0) ? vh : vl;
        *(uint4*)(sm + SM_KV + t * ATILE + r * 144 + u * 16) =
            *(const uint4*)(src + r * 64 + u * 8);
    }
    {
        const int row = tid >> 2, l4 = tid & 3;
        float* srow = S + row * AS_STRIDE;
        float mx = -1e30f;
        for (int j = l4; j < 512; j += 4) mx = fmaxf(mx, srow[j]);
        mx = fmaxf(mx, __shfl_xor_sync(0xffffffffu, mx, 1));
        mx = fmaxf(mx, __shfl_xor_sync(0xffffffffu, mx, 2));
        float sum = 0.f;
        for (int j = l4; j < 512; j += 4) {
            float e = __expf(srow[j] - mx);
            srow[j] = e;
            sum += e;
        }
        sum += __shfl_xor_sync(0xffffffffu, sum, 1);
        sum += __shfl_xor_sync(0xffffffffu, sum, 2);
        if (l4 == 0) sInv[row] = 1.0f / sum;
    }
    __syncthreads();

    // ---- Phase 3: O = e · V ----
    float accO[4][4] = {};
    const uint32_t sph = sb + SM_P, spl = sph + ATILE;
    for (int vc = 0; vc < 8; vc++) {
        uint4 pf[4];
        if (vc < 7) {
#pragma unroll
            for (int j = 0; j < 4; j++) {
                const int i = tid + j * 256;
                const int t = i >> 9, r = (i >> 3) & 63, u = i & 7;
                const __nv_bfloat16* src = ((t == 0) ? vh : vl) + (size_t)(vc + 1) * 64 * 64;
                pf[j] = *(const uint4*)(src + r * 64 + u * 8);
            }
        }
        // Convert e chunk -> bf16 split (SPh/SPl)
        {
            const int row = tid >> 2, c0 = (tid & 3) * 16;
            const float* sr = S + row * AS_STRIDE + vc * 64 + c0;
            char* ph = sm + SM_P + row * 144 + c0 * 2;
            char* pl = ph + ATILE;
#pragma unroll
            for (int c = 0; c < 16; c += 2) {
                float2 v = *(const float2*)(sr + c);
                uint32_t hi, lo;
                split2(v.x, v.y, hi, lo);
                *(uint32_t*)(ph + c * 2) = hi;
                *(uint32_t*)(pl + c * 2) = lo;
            }
        }
        __syncthreads();

        const uint32_t cb = skv + (vc & 1) * 2 * ATILE;
#pragma unroll
        for (int ks = 0; ks < 4; ks++) {
            uint32_t pfh[4], pfl[4];
            const uint32_t ro = (mw * 16 + lrow) * 144 + ks * 32 + lcolb;
            ldmx4(pfh, sph + ro);
            ldmx4(pfl, spl + ro);
            uint32_t vbh[8], vbl[8];
#pragma unroll
            for (int np = 0; np < 2; np++) {
                const uint32_t ad = (ks * 16 + (l & 7) + (((l >> 3) & 1) << 3)) * 144
                                  + (nw * 32 + np * 16 + ((l >> 4) << 3)) * 2;
                ldmx4t(&vbh[np * 4], cb + ad);
                ldmx4t(&vbl[np * 4], cb + ATILE + ad);
            }
#pragma unroll
            for (int nt = 0; nt < 4; nt++) {
                const int np = nt >> 1, q = nt & 1;
                mma_bf16(accO[nt], pfh, vbh[np * 4 + 2 * q], vbh[np * 4 + 2 * q + 1]);
                mma_bf16(accO[nt], pfh, vbl[np * 4 + 2 * q], vbl[np * 4 + 2 * q + 1]);
                mma_bf16(accO[nt], pfl, vbh[np * 4 + 2 * q], vbh[np * 4 + 2 * q + 1]);
            }
        }
        if (vc < 7) {
#pragma unroll
            for (int j = 0; j < 4; j++) {
                const int i = tid + j * 256;
                const int t = i >> 9, r = (i >> 3) & 63, u = i & 7;
                char* dst = sm + SM_KV + ((vc + 1) & 1) * 2 * ATILE + t * ATILE;
                *(uint4*)(dst + r * 144 + u * 16) = pf[j];
            }
        }
        __syncthreads();
    }

    // ---- Epilogue: O * inv, split -> g_oh/g_ol merged-head token-major ----
    const int h  = bph % NHEAD;
    const int bp = bph / NHEAD;
    const int mrow0 = mw * 16 + (l >> 2);
#pragma unroll
    for (int half = 0; half < 2; half++) {
        const int m = mrow0 + half * 8;
        const float inv = sInv[m];
        const size_t grow = ((size_t)bp * SEQ + qt * 64 + m) * CDIM + h * DHEAD;
#pragma unroll
        for (int nt = 0; nt < 4; nt++) {
            const int n = nw * 32 + nt * 8 + 2 * (l & 3);
            uint32_t hi, lo;
            split2(accO[nt][half * 2 + 0] * inv, accO[nt][half * 2 + 1] * inv, hi, lo);
            *(uint32_t*)(g_oh + grow + n) = hi;
            *(uint32_t*)(g_ol + grow + n) = lo;
        }
    }
}

// ---------------------------------------------------------------------------
extern "C" void kernel_launch(void* const* d_in, const int* in_sizes, int n_in,
                              void* d_out, int out_size)
{
    const float* x     = (const float*)d_in[0];  // (8,4,512,768)
    const float* Wqkv  = (const float*)d_in[1];  // (2304,768)
    const float* Wproj = (const float*)d_in[2];  // (768,768)
    const float* bproj = (const float*)d_in[3];  // (768,)
    float* out = (float*)d_out;

    cudaFuncSetAttribute(gemm_tc<0>, cudaFuncAttributeMaxDynamicSharedMemorySize, GSMEM);
    cudaFuncSetAttribute(gemm_tc<1>, cudaFuncAttributeMaxDynamicSharedMemorySize, GSMEM);
    cudaFuncSetAttribute(attn_tc, cudaFuncAttributeMaxDynamicSharedMemorySize, ATTN_SMEM);

    const int nx4 = MTOK * CDIM / 4;
    const int nq4 = 3 * CDIM * CDIM / 4;
    const int np4 = CDIM * CDIM / 4;

    split_bf16<<<(nx4 + 255) / 256, 256>>>(x, 0, nx4);
    split_bf16<<<(nq4 + 255) / 256, 256>>>(Wqkv, 1, nq4);
    split_bf16<<<(np4 + 255) / 256, 256>>>(Wproj, 2, np4);

    // QKV projection: (16384 x 2304 x 768); epilogue emits q/k/v bf16 splits
    gemm_tc<0><<<dim3(3 * CDIM / 128, MTOK / 128), 256, GSMEM>>>(nullptr, nullptr);

    // Tensor-core attention; epilogue emits g_oh/g_ol bf16 splits
    attn_tc<<<dim3(BPDIM * NHEAD, SEQ / 64), 256, ATTN_SMEM>>>();

    // Output projection: (16384 x 768 x 768) + bias -> d_out
    gemm_tc<1><<<dim3(CDIM / 128, MTOK / 128), 256, GSMEM>>>(out, bproj);
}

// round 5
// speedup vs baseline: 2.5926x; 1.1689x over previous
#include <cuda_runtime.h>
#include <cuda_bf16.h>
#include <math.h>
#include <stdint.h>

// Problem dims
#define SEQ    512
#define NHEAD  12
#define DHEAD  64
#define CDIM   768
#define BPDIM  32              // B*P = 8*4
#define MTOK   (BPDIM * SEQ)   // 16384 tokens
#define QSCALE 0.125f          // 64^-0.5

// ---------------------------------------------------------------------------
// Device-global scratch (allocation-free per harness rules)
// ---------------------------------------------------------------------------
#define HELEMS ((size_t)BPDIM * NHEAD * SEQ * DHEAD)   // 12.58M

// q/k/v as bf16 two-term splits, head-major [bp*12+h][n][hd]; q pre-scaled
__device__ __nv_bfloat16 g_qh[HELEMS];
__device__ __nv_bfloat16 g_ql[HELEMS];
__device__ __nv_bfloat16 g_kh[HELEMS];
__device__ __nv_bfloat16 g_kl[HELEMS];
__device__ __nv_bfloat16 g_vh[HELEMS];
__device__ __nv_bfloat16 g_vl[HELEMS];

// bf16 two-term splits for GEMM inputs / attention output (token-major)
__device__ __nv_bfloat16 g_xh[(size_t)MTOK * CDIM];
__device__ __nv_bfloat16 g_xl[(size_t)MTOK * CDIM];
__device__ __nv_bfloat16 g_oh[(size_t)MTOK * CDIM];
__device__ __nv_bfloat16 g_ol[(size_t)MTOK * CDIM];
__device__ __nv_bfloat16 g_wqh[(size_t)3 * CDIM * CDIM];
__device__ __nv_bfloat16 g_wql[(size_t)3 * CDIM * CDIM];
__device__ __nv_bfloat16 g_wph[(size_t)CDIM * CDIM];
__device__ __nv_bfloat16 g_wpl[(size_t)CDIM * CDIM];

// ---------------------------------------------------------------------------
// Base-ISA tensor helpers (mma.sync + ldmatrix + cp.async — sm_103 base target)
// ---------------------------------------------------------------------------
__device__ __forceinline__ uint32_t smem_u32(const void* p) {
    uint32_t a;
    asm("{ .reg .u64 t; cvta.to.shared.u64 t, %1; cvt.u32.u64 %0, t; }"
        : "=r"(a) : "l"(p));
    return a;
}

__device__ __forceinline__ void ldmx4(uint32_t* r, uint32_t addr) {
    asm volatile("ldmatrix.sync.aligned.m8n8.x4.shared.b16 {%0,%1,%2,%3}, [%4];"
                 : "=r"(r[0]), "=r"(r[1]), "=r"(r[2]), "=r"(r[3]) : "r"(addr));
}
__device__ __forceinline__ void ldmx4t(uint32_t* r, uint32_t addr) {
    asm volatile("ldmatrix.sync.aligned.m8n8.x4.trans.shared.b16 {%0,%1,%2,%3}, [%4];"
                 : "=r"(r[0]), "=r"(r[1]), "=r"(r[2]), "=r"(r[3]) : "r"(addr));
}

__device__ __forceinline__ void mma_bf16(float* c, const uint32_t* a,
                                         uint32_t b0, uint32_t b1) {
    asm volatile(
        "mma.sync.aligned.m16n8k16.row.col.f32.bf16.bf16.f32 "
        "{%0,%1,%2,%3}, {%4,%5,%6,%7}, {%8,%9}, {%0,%1,%2,%3};"
        : "+f"(c[0]), "+f"(c[1]), "+f"(c[2]), "+f"(c[3])
        : "r"(a[0]), "r"(a[1]), "r"(a[2]), "r"(a[3]), "r"(b0), "r"(b1));
}

__device__ __forceinline__ void cp16(uint32_t dst, const void* src) {
    asm volatile("cp.async.cg.shared.global [%0], [%1], 16;"
                 :: "r"(dst), "l"(src) : "memory");
}
#define CP_COMMIT() asm volatile("cp.async.commit_group;" ::: "memory")
#define CP_WAIT1()  asm volatile("cp.async.wait_group 1;" ::: "memory")

__device__ __forceinline__ void split2(float a0, float a1,
                                       uint32_t& hi, uint32_t& lo) {
    __nv_bfloat16 h0 = __float2bfloat16_rn(a0);
    __nv_bfloat16 h1 = __float2bfloat16_rn(a1);
    __nv_bfloat16 l0 = __float2bfloat16_rn(a0 - __bfloat162float(h0));
    __nv_bfloat16 l1 = __float2bfloat16_rn(a1 - __bfloat162float(h1));
    __nv_bfloat162 hh(h0, h1), ll(l0, l1);
    hi = *(uint32_t*)&hh;
    lo = *(uint32_t*)&ll;
}

// ---------------------------------------------------------------------------
// bf16 split kernel: hi = bf16(x), lo = bf16(x - hi).  sel: 0=x 1=Wqkv 2=Wproj
// ---------------------------------------------------------------------------
__global__ void split_bf16(const float* __restrict__ in, int sel, int n4)
{
    __nv_bfloat16 *hi, *lo;
    if (sel == 0)      { hi = g_xh;  lo = g_xl; }
    else if (sel == 1) { hi = g_wqh; lo = g_wql; }
    else               { hi = g_wph; lo = g_wpl; }

    int i = blockIdx.x * blockDim.x + threadIdx.x;
    if (i >= n4) return;
    float4 v = ((const float4*)in)[i];
    uint32_t h01, l01, h23, l23;
    split2(v.x, v.y, h01, l01);
    split2(v.z, v.w, h23, l23);
    ((uint32_t*)hi)[2 * i]     = h01;
    ((uint32_t*)hi)[2 * i + 1] = h23;
    ((uint32_t*)lo)[2 * i]     = l01;
    ((uint32_t*)lo)[2 * i + 1] = l23;
}

// ---------------------------------------------------------------------------
// Tensor-core GEMM (NT): C[m,d] = sum_k A[m,k]*B[d,k]. bf16 split, 3 products.
// CTA 128x128, BK=32, 8 warps (warp tile 64x32), 3-stage cp.async pipeline,
// XOR-swizzled 64B rows (conflict-free ldmatrix + cp.async stores).
// SMEM: 4 tiles (Ah,Al,Bh,Bl) x 8192B = 32KB/stage, 3 stages = 96KB -> 2 CTA/SM.
// MODE 0: A=x split, B=Wqkv split; epilogue splits+scatters to g_{q,k,v}{h,l}.
// MODE 1: A=g_o split, B=Wproj split; +bias -> d_out (fp32).
// ---------------------------------------------------------------------------
#define GT_B    8192
#define GSTG_B  (4 * GT_B)      // 32768
#define GSMEM   (3 * GSTG_B)    // 98304
#define NCHUNK  (CDIM / 32)     // 24

template <int MODE>
__global__ __launch_bounds__(256, 2)
void gemm_tc(float* __restrict__ Cout, const float* __restrict__ bias)
{
    extern __shared__ char smem[];
    const uint32_t sb = smem_u32(smem);
    const int tid = threadIdx.x;
    const int l   = tid & 31;
    const int warp = tid >> 5;
    const int wm = warp & 1;
    const int wn = warp >> 1;
    const int bn = blockIdx.x, bm = blockIdx.y;
    const int K = CDIM;

    const __nv_bfloat16* pAh = (MODE == 0) ? g_xh : g_oh;
    const __nv_bfloat16* pAl = (MODE == 0) ? g_xl : g_ol;
    const __nv_bfloat16* pBh = (MODE == 0) ? g_wqh : g_wph;
    const __nv_bfloat16* pBl = (MODE == 0) ? g_wql : g_wpl;

    const __nv_bfloat16* srcs[4] = {
        pAh + (size_t)(bm * 128) * K, pAl + (size_t)(bm * 128) * K,
        pBh + (size_t)(bn * 128) * K, pBl + (size_t)(bn * 128) * K };

    const int lrow  = l & 15;
    const int lhalf = l >> 4;           // 0/1 -> +0/+16B logical

    float acc[4][4][4];
#pragma unroll
    for (int i = 0; i < 4; i++)
#pragma unroll
        for (int j = 0; j < 4; j++)
#pragma unroll
            for (int q = 0; q < 4; q++) acc[i][j][q] = 0.f;

    // Pre-split loader indices (same every chunk)
    const int ldr_t = tid >> 7;                 // used with j-offset below
    (void)ldr_t;

#define LOAD_CHUNK(c, st)                                                      \
    do {                                                                       \
        _Pragma("unroll")                                                      \
        for (int j = 0; j < 8; j++) {                                          \
            const int i = tid + j * 256;                                       \
            const int t = i >> 9, r = (i >> 2) & 127, u = i & 3;               \
            const uint32_t dst = sb + (st) * GSTG_B + t * GT_B + r * 64        \
                               + ((u ^ ((r >> 1) & 3)) << 4);                  \
            cp16(dst, srcs[t] + (size_t)r * K + (c) * 32 + u * 8);             \
        }                                                                      \
        CP_COMMIT();                                                           \
    } while (0)

    LOAD_CHUNK(0, 0);
    LOAD_CHUNK(1, 1);

    for (int c = 0; c < NCHUNK; c++) {
        CP_WAIT1();
        __syncthreads();
        if (c + 2 < NCHUNK) {
            const int st = (c + 2) % 3;
            LOAD_CHUNK(c + 2, st);
        } else {
            CP_COMMIT();   // empty group keeps wait_group semantics at the tail
        }

        const uint32_t stg = sb + (c % 3) * GSTG_B;
#pragma unroll
        for (int s = 0; s < 2; s++) {
            const int slot = s * 2 + lhalf;
            uint32_t bh[8], bl[8];
#pragma unroll
            for (int np = 0; np < 2; np++) {
                const int R = wn * 32 + np * 16 + lrow;
                const uint32_t off = R * 64 + ((slot ^ ((R >> 1) & 3)) << 4);
                ldmx4(&bh[np * 4], stg + 2 * GT_B + off);
                ldmx4(&bl[np * 4], stg + 3 * GT_B + off);
            }
#pragma unroll
            for (int mt = 0; mt < 4; mt++) {
                const int R = wm * 64 + mt * 16 + lrow;
                const uint32_t off = R * 64 + ((slot ^ ((R >> 1) & 3)) << 4);
                uint32_t ah[4], al[4];
                ldmx4(ah, stg + off);
                ldmx4(al, stg + GT_B + off);
#pragma unroll
                for (int nt = 0; nt < 4; nt++) {
                    const int np = nt >> 1, q = nt & 1;
                    mma_bf16(acc[mt][nt], ah, bh[np * 4 + q], bh[np * 4 + q + 2]);
                    mma_bf16(acc[mt][nt], ah, bl[np * 4 + q], bl[np * 4 + q + 2]);
                    mma_bf16(acc[mt][nt], al, bh[np * 4 + q], bh[np * 4 + q + 2]);
                }
            }
        }
    }
#undef LOAD_CHUNK

#pragma unroll
    for (int mt = 0; mt < 4; mt++) {
#pragma unroll
        for (int nt = 0; nt < 4; nt++) {
            const int m0 = bm * 128 + wm * 64 + mt * 16 + (l >> 2);
            const int d  = bn * 128 + wn * 32 + nt * 8 + 2 * (l & 3);
#pragma unroll
            for (int half = 0; half < 2; half++) {
                const int m = m0 + half * 8;
                const float v0 = acc[mt][nt][half * 2 + 0];
                const float v1 = acc[mt][nt][half * 2 + 1];
                if (MODE == 0) {
                    const int bp = m >> 9;
                    const int n  = m & (SEQ - 1);
                    const int ss  = d / CDIM;
                    const int rem = d - ss * CDIM;
                    const int h   = rem >> 6;
                    const int hd  = rem & 63;
                    const size_t base = ((size_t)(bp * NHEAD + h) * SEQ + n) * DHEAD + hd;
                    const float sc = (ss == 0) ? QSCALE : 1.0f;
                    uint32_t hi, lo;
                    split2(v0 * sc, v1 * sc, hi, lo);
                    __nv_bfloat16* dh = (ss == 0) ? g_qh : (ss == 1) ? g_kh : g_vh;
                    __nv_bfloat16* dl = (ss == 0) ? g_ql : (ss == 1) ? g_kl : g_vl;
                    *(uint32_t*)(dh + base) = hi;
                    *(uint32_t*)(dl + base) = lo;
                } else {
                    float2 bv = *(const float2*)(bias + d);
                    *(float2*)(Cout + (size_t)m * CDIM + d) =
                        make_float2(v0 + bv.x, v1 + bv.y);
                }
            }
        }
    }
}

// ---------------------------------------------------------------------------
// Tensor-core attention (unchanged from round 4 — known correct)
// ---------------------------------------------------------------------------
#define AS_STRIDE 524
#define ATILE     9216                       // 64 rows * 144B
#define SM_Q      (64 * AS_STRIDE * 4)       // 134144: SQh, SQl
#define SM_KV     (SM_Q + 2 * ATILE)         // 152576: 2 bufs x {h,l}
#define SM_P      (SM_KV + 4 * ATILE)        // 189440: SPh, SPl
#define SM_INV    (SM_P + 2 * ATILE)         // 207872
#define ATTN_SMEM (SM_INV + 256)             // 208128

__global__ __launch_bounds__(256, 1)
void attn_tc()
{
    extern __shared__ char sm[];
    float* S = (float*)sm;
    float* sInv = (float*)(sm + SM_INV);
    const uint32_t sb = smem_u32(sm);
    const int tid = threadIdx.x, l = tid & 31, w = tid >> 5;
    const int mw = w & 3, nw = w >> 2;
    const int bph = blockIdx.x, qt = blockIdx.y;
    const size_t hoff = (size_t)bph * SEQ * DHEAD;
    const __nv_bfloat16* qh = g_qh + hoff + (size_t)qt * 64 * DHEAD;
    const __nv_bfloat16* ql = g_ql + hoff + (size_t)qt * 64 * DHEAD;
    const __nv_bfloat16* kh = g_kh + hoff;
    const __nv_bfloat16* kl = g_kl + hoff;
    const __nv_bfloat16* vh = g_vh + hoff;
    const __nv_bfloat16* vl = g_vl + hoff;

    const int lrow  = l & 15;
    const int lcolb = (l >> 4) << 4;

    for (int i = tid; i < 2048; i += 256) {
        const int t = i >> 9, r = (i >> 3) & 63, u = i & 7;
        const __nv_bfloat16* src = (t == 0) ? qh : (t == 1) ? ql : (t == 2) ? kh : kl;
        char* dst = sm + ((t < 2) ? (SM_Q + t * ATILE) : (SM_KV + (t - 2) * ATILE));
        *(uint4*)(dst + r * 144 + u * 16) = *(const uint4*)(src + r * 64 + u * 8);
    }
    __syncthreads();

    uint32_t qfh[4][4], qfl[4][4];
    {
        const uint32_t sqh = sb + SM_Q, sql = sqh + ATILE;
#pragma unroll
        for (int ks = 0; ks < 4; ks++) {
            const uint32_t ro = (mw * 16 + lrow) * 144 + ks * 32 + lcolb;
            ldmx4(qfh[ks], sqh + ro);
            ldmx4(qfl[ks], sql + ro);
        }
    }

    const uint32_t skv = sb + SM_KV;

    for (int kc = 0; kc < 8; kc++) {
        uint4 pf[4];
        if (kc < 7) {
#pragma unroll
            for (int j = 0; j < 4; j++) {
                const int i = tid + j * 256;
                const int t = i >> 9, r = (i >> 3) & 63, u = i & 7;
                const __nv_bfloat16* src = ((t == 0) ? kh : kl) + (size_t)(kc + 1) * 64 * 64;
                pf[j] = *(const uint4*)(src + r * 64 + u * 8);
            }
        }
        const uint32_t cb = skv + (kc & 1) * 2 * ATILE;
        float accS[4][4] = {};
#pragma unroll
        for (int ks = 0; ks < 4; ks++) {
            uint32_t kbh[8], kbl[8];
#pragma unroll
            for (int np = 0; np < 2; np++) {
                const uint32_t ro = (nw * 32 + np * 16 + lrow) * 144 + ks * 32 + lcolb;
                ldmx4(&kbh[np * 4], cb + ro);
                ldmx4(&kbl[np * 4], cb + ATILE + ro);
            }
#pragma unroll
            for (int nt = 0; nt < 4; nt++) {
                const int np = nt >> 1, q = nt & 1;
                mma_bf16(accS[nt], qfh[ks], kbh[np * 4 + q], kbh[np * 4 + q + 2]);
                mma_bf16(accS[nt], qfh[ks], kbl[np * 4 + q], kbl[np * 4 + q + 2]);
                mma_bf16(accS[nt], qfl[ks], kbh[np * 4 + q], kbh[np * 4 + q + 2]);
            }
        }
#pragma unroll
        for (int nt = 0; nt < 4; nt++) {
            const int row = mw * 16 + (l >> 2);
            const int col = kc * 64 + nw * 32 + nt * 8 + 2 * (l & 3);
            *(float2*)&S[row * AS_STRIDE + col]       = make_float2(accS[nt][0], accS[nt][1]);
            *(float2*)&S[(row + 8) * AS_STRIDE + col] = make_float2(accS[nt][2], accS[nt][3]);
        }
        if (kc < 7) {
#pragma unroll
            for (int j = 0; j < 4; j++) {
                const int i = tid + j * 256;
                const int t = i >> 9, r = (i >> 3) & 63, u = i & 7;
                char* dst = sm + SM_KV + ((kc + 1) & 1) * 2 * ATILE + t * ATILE;
                *(uint4*)(dst + r * 144 + u * 16) = pf[j];
            }
        }
        __syncthreads();
    }

    for (int i = tid; i < 1024; i += 256) {
        const int t = i >> 9, r = (i >> 3) & 63, u = i & 7;
        const __nv_bfloat16* src = (t == 0) ? vh : vl;
        *(uint4*)(sm + SM_KV + t * ATILE + r * 144 + u * 16) =
            *(const uint4*)(src + r * 64 + u * 8);
    }
    {
        const int row = tid >> 2, l4 = tid & 3;
        float* srow = S + row * AS_STRIDE;
        float mx = -1e30f;
        for (int j = l4; j < 512; j += 4) mx = fmaxf(mx, srow[j]);
        mx = fmaxf(mx, __shfl_xor_sync(0xffffffffu, mx, 1));
        mx = fmaxf(mx, __shfl_xor_sync(0xffffffffu, mx, 2));
        float sum = 0.f;
        for (int j = l4; j < 512; j += 4) {
            float e = __expf(srow[j] - mx);
            srow[j] = e;
            sum += e;
        }
        sum += __shfl_xor_sync(0xffffffffu, sum, 1);
        sum += __shfl_xor_sync(0xffffffffu, sum, 2);
        if (l4 == 0) sInv[row] = 1.0f / sum;
    }
    __syncthreads();

    float accO[4][4] = {};
    const uint32_t sph = sb + SM_P, spl = sph + ATILE;
    for (int vc = 0; vc < 8; vc++) {
        uint4 pf[4];
        if (vc < 7) {
#pragma unroll
            for (int j = 0; j < 4; j++) {
                const int i = tid + j * 256;
                const int t = i >> 9, r = (i >> 3) & 63, u = i & 7;
                const __nv_bfloat16* src = ((t == 0) ? vh : vl) + (size_t)(vc + 1) * 64 * 64;
                pf[j] = *(const uint4*)(src + r * 64 + u * 8);
            }
        }
        {
            const int row = tid >> 2, c0 = (tid & 3) * 16;
            const float* sr = S + row * AS_STRIDE + vc * 64 + c0;
            char* ph = sm + SM_P + row * 144 + c0 * 2;
            char* pl = ph + ATILE;
#pragma unroll
            for (int c = 0; c < 16; c += 2) {
                float2 v = *(const float2*)(sr + c);
                uint32_t hi, lo;
                split2(v.x, v.y, hi, lo);
                *(uint32_t*)(ph + c * 2) = hi;
                *(uint32_t*)(pl + c * 2) = lo;
            }
        }
        __syncthreads();

        const uint32_t cb = skv + (vc & 1) * 2 * ATILE;
#pragma unroll
        for (int ks = 0; ks < 4; ks++) {
            uint32_t pfh[4], pfl[4];
            const uint32_t ro = (mw * 16 + lrow) * 144 + ks * 32 + lcolb;
            ldmx4(pfh, sph + ro);
            ldmx4(pfl, spl + ro);
            uint32_t vbh[8], vbl[8];
#pragma unroll
            for (int np = 0; np < 2; np++) {
                const uint32_t ad = (ks * 16 + (l & 7) + (((l >> 3) & 1) << 3)) * 144
                                  + (nw * 32 + np * 16 + ((l >> 4) << 3)) * 2;
                ldmx4t(&vbh[np * 4], cb + ad);
                ldmx4t(&vbl[np * 4], cb + ATILE + ad);
            }
#pragma unroll
            for (int nt = 0; nt < 4; nt++) {
                const int np = nt >> 1, q = nt & 1;
                mma_bf16(accO[nt], pfh, vbh[np * 4 + 2 * q], vbh[np * 4 + 2 * q + 1]);
                mma_bf16(accO[nt], pfh, vbl[np * 4 + 2 * q], vbl[np * 4 + 2 * q + 1]);
                mma_bf16(accO[nt], pfl, vbh[np * 4 + 2 * q], vbh[np * 4 + 2 * q + 1]);
            }
        }
        if (vc < 7) {
#pragma unroll
            for (int j = 0; j < 4; j++) {
                const int i = tid + j * 256;
                const int t = i >> 9, r = (i >> 3) & 63, u = i & 7;
                char* dst = sm + SM_KV + ((vc + 1) & 1) * 2 * ATILE + t * ATILE;
                *(uint4*)(dst + r * 144 + u * 16) = pf[j];
            }
        }
        __syncthreads();
    }

    const int h  = bph % NHEAD;
    const int bp = bph / NHEAD;
    const int mrow0 = mw * 16 + (l >> 2);
#pragma unroll
    for (int half = 0; half < 2; half++) {
        const int m = mrow0 + half * 8;
        const float inv = sInv[m];
        const size_t grow = ((size_t)bp * SEQ + qt * 64 + m) * CDIM + h * DHEAD;
#pragma unroll
        for (int nt = 0; nt < 4; nt++) {
            const int n = nw * 32 + nt * 8 + 2 * (l & 3);
            uint32_t hi, lo;
            split2(accO[nt][half * 2 + 0] * inv, accO[nt][half * 2 + 1] * inv, hi, lo);
            *(uint32_t*)(g_oh + grow + n) = hi;
            *(uint32_t*)(g_ol + grow + n) = lo;
        }
    }
}

// ---------------------------------------------------------------------------
extern "C" void kernel_launch(void* const* d_in, const int* in_sizes, int n_in,
                              void* d_out, int out_size)
{
    const float* x     = (const float*)d_in[0];  // (8,4,512,768)
    const float* Wqkv  = (const float*)d_in[1];  // (2304,768)
    const float* Wproj = (const float*)d_in[2];  // (768,768)
    const float* bproj = (const float*)d_in[3];  // (768,)
    float* out = (float*)d_out;

    cudaFuncSetAttribute(gemm_tc<0>, cudaFuncAttributeMaxDynamicSharedMemorySize, GSMEM);
    cudaFuncSetAttribute(gemm_tc<1>, cudaFuncAttributeMaxDynamicSharedMemorySize, GSMEM);
    cudaFuncSetAttribute(attn_tc, cudaFuncAttributeMaxDynamicSharedMemorySize, ATTN_SMEM);

    const int nx4 = MTOK * CDIM / 4;
    const int nq4 = 3 * CDIM * CDIM / 4;
    const int np4 = CDIM * CDIM / 4;

    split_bf16<<<(nx4 + 255) / 256, 256>>>(x, 0, nx4);
    split_bf16<<<(nq4 + 255) / 256, 256>>>(Wqkv, 1, nq4);
    split_bf16<<<(np4 + 255) / 256, 256>>>(Wproj, 2, np4);

    // QKV projection: (16384 x 2304 x 768); epilogue emits q/k/v bf16 splits
    gemm_tc<0><<<dim3(3 * CDIM / 128, MTOK / 128), 256, GSMEM>>>(nullptr, nullptr);

    // Tensor-core attention; epilogue emits g_oh/g_ol bf16 splits
    attn_tc<<<dim3(BPDIM * NHEAD, SEQ / 64), 256, ATTN_SMEM>>>();

    // Output projection: (16384 x 768 x 768) + bias -> d_out
    gemm_tc<1><<<dim3(CDIM / 128, MTOK / 128), 256, GSMEM>>>(out, bproj);
}

// round 6
// speedup vs baseline: 3.3208x; 1.2809x over previous
#include <cuda_runtime.h>
#include <cuda_bf16.h>
#include <math.h>
#include <stdint.h>

// Problem dims
#define SEQ    512
#define NHEAD  12
#define DHEAD  64
#define CDIM   768
#define BPDIM  32              // B*P = 8*4
#define MTOK   (BPDIM * SEQ)   // 16384 tokens
#define QSCALE 0.125f          // 64^-0.5

// ---------------------------------------------------------------------------
// Device-global scratch (allocation-free per harness rules)
// ---------------------------------------------------------------------------
#define HELEMS ((size_t)BPDIM * NHEAD * SEQ * DHEAD)   // 12.58M

__device__ __nv_bfloat16 g_qh[HELEMS];
__device__ __nv_bfloat16 g_ql[HELEMS];
__device__ __nv_bfloat16 g_kh[HELEMS];
__device__ __nv_bfloat16 g_kl[HELEMS];
__device__ __nv_bfloat16 g_vh[HELEMS];
__device__ __nv_bfloat16 g_vl[HELEMS];

__device__ __nv_bfloat16 g_xh[(size_t)MTOK * CDIM];
__device__ __nv_bfloat16 g_xl[(size_t)MTOK * CDIM];
__device__ __nv_bfloat16 g_oh[(size_t)MTOK * CDIM];
__device__ __nv_bfloat16 g_ol[(size_t)MTOK * CDIM];
__device__ __nv_bfloat16 g_wqh[(size_t)3 * CDIM * CDIM];
__device__ __nv_bfloat16 g_wql[(size_t)3 * CDIM * CDIM];
__device__ __nv_bfloat16 g_wph[(size_t)CDIM * CDIM];
__device__ __nv_bfloat16 g_wpl[(size_t)CDIM * CDIM];

// ---------------------------------------------------------------------------
// Base-ISA tensor helpers (mma.sync + ldmatrix + cp.async — sm_103 base target)
// ---------------------------------------------------------------------------
__device__ __forceinline__ uint32_t smem_u32(const void* p) {
    uint32_t a;
    asm("{ .reg .u64 t; cvta.to.shared.u64 t, %1; cvt.u32.u64 %0, t; }"
        : "=r"(a) : "l"(p));
    return a;
}

__device__ __forceinline__ void ldmx4(uint32_t* r, uint32_t addr) {
    asm volatile("ldmatrix.sync.aligned.m8n8.x4.shared.b16 {%0,%1,%2,%3}, [%4];"
                 : "=r"(r[0]), "=r"(r[1]), "=r"(r[2]), "=r"(r[3]) : "r"(addr));
}
__device__ __forceinline__ void ldmx4t(uint32_t* r, uint32_t addr) {
    asm volatile("ldmatrix.sync.aligned.m8n8.x4.trans.shared.b16 {%0,%1,%2,%3}, [%4];"
                 : "=r"(r[0]), "=r"(r[1]), "=r"(r[2]), "=r"(r[3]) : "r"(addr));
}

__device__ __forceinline__ void mma_bf16(float* c, const uint32_t* a,
                                         uint32_t b0, uint32_t b1) {
    asm volatile(
        "mma.sync.aligned.m16n8k16.row.col.f32.bf16.bf16.f32 "
        "{%0,%1,%2,%3}, {%4,%5,%6,%7}, {%8,%9}, {%0,%1,%2,%3};"
        : "+f"(c[0]), "+f"(c[1]), "+f"(c[2]), "+f"(c[3])
        : "r"(a[0]), "r"(a[1]), "r"(a[2]), "r"(a[3]), "r"(b0), "r"(b1));
}

__device__ __forceinline__ void cp16(uint32_t dst, const void* src) {
    asm volatile("cp.async.cg.shared.global [%0], [%1], 16;"
                 :: "r"(dst), "l"(src) : "memory");
}
#define CP_COMMIT() asm volatile("cp.async.commit_group;" ::: "memory")
#define CP_WAIT1()  asm volatile("cp.async.wait_group 1;" ::: "memory")
#define CP_WAIT0()  asm volatile("cp.async.wait_group 0;" ::: "memory")

__device__ __forceinline__ void split2(float a0, float a1,
                                       uint32_t& hi, uint32_t& lo) {
    __nv_bfloat16 h0 = __float2bfloat16_rn(a0);
    __nv_bfloat16 h1 = __float2bfloat16_rn(a1);
    __nv_bfloat16 l0 = __float2bfloat16_rn(a0 - __bfloat162float(h0));
    __nv_bfloat16 l1 = __float2bfloat16_rn(a1 - __bfloat162float(h1));
    __nv_bfloat162 hh(h0, h1), ll(l0, l1);
    hi = *(uint32_t*)&hh;
    lo = *(uint32_t*)&ll;
}

// ---------------------------------------------------------------------------
// bf16 split kernel: hi = bf16(x), lo = bf16(x - hi).  sel: 0=x 1=Wqkv 2=Wproj
// ---------------------------------------------------------------------------
__global__ void split_bf16(const float* __restrict__ in, int sel, int n4)
{
    __nv_bfloat16 *hi, *lo;
    if (sel == 0)      { hi = g_xh;  lo = g_xl; }
    else if (sel == 1) { hi = g_wqh; lo = g_wql; }
    else               { hi = g_wph; lo = g_wpl; }

    int i = blockIdx.x * blockDim.x + threadIdx.x;
    if (i >= n4) return;
    float4 v = ((const float4*)in)[i];
    uint32_t h01, l01, h23, l23;
    split2(v.x, v.y, h01, l01);
    split2(v.z, v.w, h23, l23);
    ((uint32_t*)hi)[2 * i]     = h01;
    ((uint32_t*)hi)[2 * i + 1] = h23;
    ((uint32_t*)lo)[2 * i]     = l01;
    ((uint32_t*)lo)[2 * i + 1] = l23;
}

// ---------------------------------------------------------------------------
// Tensor-core GEMM (unchanged from round 5 — 3-stage cp.async, 2 CTA/SM)
// ---------------------------------------------------------------------------
#define GT_B    8192
#define GSTG_B  (4 * GT_B)      // 32768
#define GSMEM   (3 * GSTG_B)    // 98304
#define NCHUNK  (CDIM / 32)     // 24

template <int MODE>
__global__ __launch_bounds__(256, 2)
void gemm_tc(float* __restrict__ Cout, const float* __restrict__ bias)
{
    extern __shared__ char smem[];
    const uint32_t sb = smem_u32(smem);
    const int tid = threadIdx.x;
    const int l   = tid & 31;
    const int warp = tid >> 5;
    const int wm = warp & 1;
    const int wn = warp >> 1;
    const int bn = blockIdx.x, bm = blockIdx.y;
    const int K = CDIM;

    const __nv_bfloat16* pAh = (MODE == 0) ? g_xh : g_oh;
    const __nv_bfloat16* pAl = (MODE == 0) ? g_xl : g_ol;
    const __nv_bfloat16* pBh = (MODE == 0) ? g_wqh : g_wph;
    const __nv_bfloat16* pBl = (MODE == 0) ? g_wql : g_wpl;

    const __nv_bfloat16* srcs[4] = {
        pAh + (size_t)(bm * 128) * K, pAl + (size_t)(bm * 128) * K,
        pBh + (size_t)(bn * 128) * K, pBl + (size_t)(bn * 128) * K };

    const int lrow  = l & 15;
    const int lhalf = l >> 4;

    float acc[4][4][4];
#pragma unroll
    for (int i = 0; i < 4; i++)
#pragma unroll
        for (int j = 0; j < 4; j++)
#pragma unroll
            for (int q = 0; q < 4; q++) acc[i][j][q] = 0.f;

#define LOAD_CHUNK(c, st)                                                      \
    do {                                                                       \
        _Pragma("unroll")                                                      \
        for (int j = 0; j < 8; j++) {                                          \
            const int i = tid + j * 256;                                       \
            const int t = i >> 9, r = (i >> 2) & 127, u = i & 3;               \
            const uint32_t dst = sb + (st) * GSTG_B + t * GT_B + r * 64        \
                               + ((u ^ ((r >> 1) & 3)) << 4);                  \
            cp16(dst, srcs[t] + (size_t)r * K + (c) * 32 + u * 8);             \
        }                                                                      \
        CP_COMMIT();                                                           \
    } while (0)

    LOAD_CHUNK(0, 0);
    LOAD_CHUNK(1, 1);

    for (int c = 0; c < NCHUNK; c++) {
        CP_WAIT1();
        __syncthreads();
        if (c + 2 < NCHUNK) {
            const int st = (c + 2) % 3;
            LOAD_CHUNK(c + 2, st);
        } else {
            CP_COMMIT();
        }

        const uint32_t stg = sb + (c % 3) * GSTG_B;
#pragma unroll
        for (int s = 0; s < 2; s++) {
            const int slot = s * 2 + lhalf;
            uint32_t bh[8], bl[8];
#pragma unroll
            for (int np = 0; np < 2; np++) {
                const int R = wn * 32 + np * 16 + lrow;
                const uint32_t off = R * 64 + ((slot ^ ((R >> 1) & 3)) << 4);
                ldmx4(&bh[np * 4], stg + 2 * GT_B + off);
                ldmx4(&bl[np * 4], stg + 3 * GT_B + off);
            }
#pragma unroll
            for (int mt = 0; mt < 4; mt++) {
                const int R = wm * 64 + mt * 16 + lrow;
                const uint32_t off = R * 64 + ((slot ^ ((R >> 1) & 3)) << 4);
                uint32_t ah[4], al[4];
                ldmx4(ah, stg + off);
                ldmx4(al, stg + GT_B + off);
#pragma unroll
                for (int nt = 0; nt < 4; nt++) {
                    const int np = nt >> 1, q = nt & 1;
                    mma_bf16(acc[mt][nt], ah, bh[np * 4 + q], bh[np * 4 + q + 2]);
                    mma_bf16(acc[mt][nt], ah, bl[np * 4 + q], bl[np * 4 + q + 2]);
                    mma_bf16(acc[mt][nt], al, bh[np * 4 + q], bh[np * 4 + q + 2]);
                }
            }
        }
    }
#undef LOAD_CHUNK

#pragma unroll
    for (int mt = 0; mt < 4; mt++) {
#pragma unroll
        for (int nt = 0; nt < 4; nt++) {
            const int m0 = bm * 128 + wm * 64 + mt * 16 + (l >> 2);
            const int d  = bn * 128 + wn * 32 + nt * 8 + 2 * (l & 3);
#pragma unroll
            for (int half = 0; half < 2; half++) {
                const int m = m0 + half * 8;
                const float v0 = acc[mt][nt][half * 2 + 0];
                const float v1 = acc[mt][nt][half * 2 + 1];
                if (MODE == 0) {
                    const int bp = m >> 9;
                    const int n  = m & (SEQ - 1);
                    const int ss  = d / CDIM;
                    const int rem = d - ss * CDIM;
                    const int h   = rem >> 6;
                    const int hd  = rem & 63;
                    const size_t base = ((size_t)(bp * NHEAD + h) * SEQ + n) * DHEAD + hd;
                    const float sc = (ss == 0) ? QSCALE : 1.0f;
                    uint32_t hi, lo;
                    split2(v0 * sc, v1 * sc, hi, lo);
                    __nv_bfloat16* dh = (ss == 0) ? g_qh : (ss == 1) ? g_kh : g_vh;
                    __nv_bfloat16* dl = (ss == 0) ? g_ql : (ss == 1) ? g_kl : g_vl;
                    *(uint32_t*)(dh + base) = hi;
                    *(uint32_t*)(dl + base) = lo;
                } else {
                    float2 bv = *(const float2*)(bias + d);
                    *(float2*)(Cout + (size_t)m * CDIM + d) =
                        make_float2(v0 + bv.x, v1 + bv.y);
                }
            }
        }
    }
}

// ---------------------------------------------------------------------------
// Flash attention (online softmax, register-resident S and O).
// Block = (head, 64-query tile), 256 thr / 8 warps: mw=w&3 -> 16-query stripe,
// nw=w>>2 -> 32-key half. Per 64-key chunk: QK^T frag -> online max (one
// cross-warp exchange) -> P=exp in regs -> bf16-split A-frag -> PV mma.
// K/V (h,l) cp.async double-buffered. Final cross-warp O+sum combine in SMEM
// overlaid on retired KV buffers. SMEM 91KB -> 2 CTA/SM.
// ---------------------------------------------------------------------------
#define AT_STRIDE 144
#define AT_TILE   (64 * AT_STRIDE)          // 9216
#define ASM_Q     0
#define ASM_KV    (2 * AT_TILE)             // 18432
#define ASM_STG   (4 * AT_TILE)             // 36864 per stage (Kh,Kl,Vh,Vl)
#define ASM_MAX   (ASM_KV + 2 * ASM_STG)    // 92160
#define ASM_SUM   (ASM_MAX + 512)           // 92672
#define ASM_O     ASM_KV                    // overlay after last chunk
#define AO_STR    66
#define ATTN_SMEM (ASM_SUM + 512)           // 93184

__global__ __launch_bounds__(256, 2)
void attn_flash()
{
    extern __shared__ char sm[];
    const uint32_t sb = smem_u32(sm);
    float* smax = (float*)(sm + ASM_MAX);   // [64][2]
    float* ssum = (float*)(sm + ASM_SUM);   // [64][2]
    float* sO   = (float*)(sm + ASM_O);     // [2][64][66]

    const int tid = threadIdx.x, l = tid & 31, w = tid >> 5;
    const int mw = w & 3, nw = w >> 2;
    const int bph = blockIdx.x, qt = blockIdx.y;
    const size_t hoff = (size_t)bph * SEQ * DHEAD;
    const __nv_bfloat16* qh = g_qh + hoff + (size_t)qt * 64 * DHEAD;
    const __nv_bfloat16* ql = g_ql + hoff + (size_t)qt * 64 * DHEAD;
    const __nv_bfloat16* asrc[4] = { g_kh + hoff, g_kl + hoff,
                                     g_vh + hoff, g_vl + hoff };

    const int lrow  = l & 15;
    const int lcolb = (l >> 4) << 4;
    const int r0    = mw * 16 + (l >> 2);

    // Q tiles (h,l) via plain stores (one-time)
    for (int i = tid; i < 1024; i += 256) {
        const int t = i >> 9, r = (i >> 3) & 63, u = i & 7;
        const __nv_bfloat16* src = (t == 0) ? qh : ql;
        *(uint4*)(sm + ASM_Q + t * AT_TILE + r * AT_STRIDE + u * 16) =
            *(const uint4*)(src + r * 64 + u * 8);
    }

#define ALOAD(c, st)                                                           \
    do {                                                                       \
        _Pragma("unroll")                                                      \
        for (int j = 0; j < 8; j++) {                                          \
            const int i = tid + j * 256;                                       \
            const int t = i >> 9, r = (i >> 3) & 63, u = i & 7;                \
            cp16(sb + ASM_KV + (st) * ASM_STG + t * AT_TILE + r * AT_STRIDE    \
                     + u * 16,                                                 \
                 asrc[t] + (size_t)(c) * 64 * 64 + r * 64 + u * 8);            \
        }                                                                      \
        CP_COMMIT();                                                           \
    } while (0)

    ALOAD(0, 0);

    float accO[8][4];
#pragma unroll
    for (int i = 0; i < 8; i++)
#pragma unroll
        for (int q = 0; q < 4; q++) accO[i][q] = 0.f;
    float mrun0 = -1e30f, mrun1 = -1e30f;
    float lsum0 = 0.f, lsum1 = 0.f;

    for (int kc = 0; kc < 8; kc++) {
        if (kc < 7) { ALOAD(kc + 1, (kc + 1) & 1); CP_WAIT1(); }
        else        { CP_WAIT0(); }
        __syncthreads();

        const uint32_t stg = sb + ASM_KV + (kc & 1) * ASM_STG;

        // ---- QK^T: 16 queries x 32 keys per warp ----
        float accS[4][4] = {};
#pragma unroll
        for (int ks = 0; ks < 4; ks++) {
            uint32_t qfh[4], qfl[4];
            const uint32_t qro = (mw * 16 + lrow) * AT_STRIDE + ks * 32 + lcolb;
            ldmx4(qfh, sb + ASM_Q + qro);
            ldmx4(qfl, sb + ASM_Q + AT_TILE + qro);
            uint32_t kbh[8], kbl[8];
#pragma unroll
            for (int np = 0; np < 2; np++) {
                const uint32_t off = (nw * 32 + np * 16 + lrow) * AT_STRIDE
                                   + ks * 32 + lcolb;
                ldmx4(&kbh[np * 4], stg + off);
                ldmx4(&kbl[np * 4], stg + AT_TILE + off);
            }
#pragma unroll
            for (int nt = 0; nt < 4; nt++) {
                const int np = nt >> 1, q = nt & 1;
                mma_bf16(accS[nt], qfh, kbh[np * 4 + q], kbh[np * 4 + q + 2]);
                mma_bf16(accS[nt], qfh, kbl[np * 4 + q], kbl[np * 4 + q + 2]);
                mma_bf16(accS[nt], qfl, kbh[np * 4 + q], kbh[np * 4 + q + 2]);
            }
        }

        // ---- online softmax: chunk max (quad + cross-warp) ----
        float ml0 = -1e30f, ml1 = -1e30f;
#pragma unroll
        for (int nt = 0; nt < 4; nt++) {
            ml0 = fmaxf(ml0, fmaxf(accS[nt][0], accS[nt][1]));
            ml1 = fmaxf(ml1, fmaxf(accS[nt][2], accS[nt][3]));
        }
        ml0 = fmaxf(ml0, __shfl_xor_sync(0xffffffffu, ml0, 1));
        ml0 = fmaxf(ml0, __shfl_xor_sync(0xffffffffu, ml0, 2));
        ml1 = fmaxf(ml1, __shfl_xor_sync(0xffffffffu, ml1, 1));
        ml1 = fmaxf(ml1, __shfl_xor_sync(0xffffffffu, ml1, 2));
        if ((l & 3) == 0) {
            smax[r0 * 2 + nw]       = ml0;
            smax[(r0 + 8) * 2 + nw] = ml1;
        }
        __syncthreads();
        const float mc0 = fmaxf(smax[r0 * 2], smax[r0 * 2 + 1]);
        const float mc1 = fmaxf(smax[(r0 + 8) * 2], smax[(r0 + 8) * 2 + 1]);
        const float mn0 = fmaxf(mrun0, mc0), mn1 = fmaxf(mrun1, mc1);
        const float sc0 = __expf(mrun0 - mn0), sc1 = __expf(mrun1 - mn1);
        mrun0 = mn0; mrun1 = mn1;
        lsum0 *= sc0; lsum1 *= sc1;
#pragma unroll
        for (int nt = 0; nt < 8; nt++) {
            accO[nt][0] *= sc0; accO[nt][1] *= sc0;
            accO[nt][2] *= sc1; accO[nt][3] *= sc1;
        }

        // ---- P = exp(S - m) -> bf16-split A-frags (C-frag == A-frag trick) ----
        uint32_t Ph[2][4], Pl[2][4];
        float ps0 = 0.f, ps1 = 0.f;
#pragma unroll
        for (int kb = 0; kb < 2; kb++) {
            const float p00 = __expf(accS[2 * kb][0] - mn0);
            const float p01 = __expf(accS[2 * kb][1] - mn0);
            const float p10 = __expf(accS[2 * kb][2] - mn1);
            const float p11 = __expf(accS[2 * kb][3] - mn1);
            const float p20 = __expf(accS[2 * kb + 1][0] - mn0);
            const float p21 = __expf(accS[2 * kb + 1][1] - mn0);
            const float p30 = __expf(accS[2 * kb + 1][2] - mn1);
            const float p31 = __expf(accS[2 * kb + 1][3] - mn1);
            ps0 += p00 + p01 + p20 + p21;
            ps1 += p10 + p11 + p30 + p31;
            split2(p00, p01, Ph[kb][0], Pl[kb][0]);
            split2(p10, p11, Ph[kb][1], Pl[kb][1]);
            split2(p20, p21, Ph[kb][2], Pl[kb][2]);
            split2(p30, p31, Ph[kb][3], Pl[kb][3]);
        }
        ps0 += __shfl_xor_sync(0xffffffffu, ps0, 1);
        ps0 += __shfl_xor_sync(0xffffffffu, ps0, 2);
        ps1 += __shfl_xor_sync(0xffffffffu, ps1, 1);
        ps1 += __shfl_xor_sync(0xffffffffu, ps1, 2);
        lsum0 += ps0; lsum1 += ps1;

        // ---- PV: warp's 32 keys x full 64 dims ----
#pragma unroll
        for (int kb = 0; kb < 2; kb++) {
#pragma unroll
            for (int np = 0; np < 4; np++) {
                uint32_t vbh[4], vbl[4];
                const uint32_t ad =
                    (nw * 32 + kb * 16 + (l & 7) + (((l >> 3) & 1) << 3)) * AT_STRIDE
                    + (np * 16 + ((l >> 4) << 3)) * 2;
                ldmx4t(vbh, stg + 2 * AT_TILE + ad);
                ldmx4t(vbl, stg + 3 * AT_TILE + ad);
#pragma unroll
                for (int q = 0; q < 2; q++) {
                    const int nt = np * 2 + q;
                    mma_bf16(accO[nt], Ph[kb], vbh[2 * q], vbh[2 * q + 1]);
                    mma_bf16(accO[nt], Ph[kb], vbl[2 * q], vbl[2 * q + 1]);
                    mma_bf16(accO[nt], Pl[kb], vbh[2 * q], vbh[2 * q + 1]);
                }
            }
        }
        __syncthreads();   // stage reuse: all reads done before next ALOAD writes
    }
#undef ALOAD

    // ---- combine the two key-halves + normalize + split-store ----
    if ((l & 3) == 0) {
        ssum[r0 * 2 + nw]       = lsum0;
        ssum[(r0 + 8) * 2 + nw] = lsum1;
    }
#pragma unroll
    for (int nt = 0; nt < 8; nt++) {
        const int col = nt * 8 + 2 * (l & 3);
        *(float2*)&sO[(nw * 64 + r0) * AO_STR + col] =
            make_float2(accO[nt][0], accO[nt][1]);
        *(float2*)&sO[(nw * 64 + r0 + 8) * AO_STR + col] =
            make_float2(accO[nt][2], accO[nt][3]);
    }
    __syncthreads();

    const int h  = bph % NHEAD;
    const int bp = bph / NHEAD;
    for (int i = tid; i < 2048; i += 256) {
        const int r = i >> 5, c = (i & 31) * 2;
        const float inv = 1.0f / (ssum[r * 2] + ssum[r * 2 + 1]);
        const float o0 = (sO[r * AO_STR + c]     + sO[(64 + r) * AO_STR + c])     * inv;
        const float o1 = (sO[r * AO_STR + c + 1] + sO[(64 + r) * AO_STR + c + 1]) * inv;
        uint32_t hi, lo;
        split2(o0, o1, hi, lo);
        const size_t grow = ((size_t)bp * SEQ + qt * 64 + r) * CDIM + h * DHEAD + c;
        *(uint32_t*)(g_oh + grow) = hi;
        *(uint32_t*)(g_ol + grow) = lo;
    }
}

// ---------------------------------------------------------------------------
extern "C" void kernel_launch(void* const* d_in, const int* in_sizes, int n_in,
                              void* d_out, int out_size)
{
    const float* x     = (const float*)d_in[0];  // (8,4,512,768)
    const float* Wqkv  = (const float*)d_in[1];  // (2304,768)
    const float* Wproj = (const float*)d_in[2];  // (768,768)
    const float* bproj = (const float*)d_in[3];  // (768,)
    float* out = (float*)d_out;

    cudaFuncSetAttribute(gemm_tc<0>, cudaFuncAttributeMaxDynamicSharedMemorySize, GSMEM);
    cudaFuncSetAttribute(gemm_tc<1>, cudaFuncAttributeMaxDynamicSharedMemorySize, GSMEM);
    cudaFuncSetAttribute(attn_flash, cudaFuncAttributeMaxDynamicSharedMemorySize, ATTN_SMEM);

    const int nx4 = MTOK * CDIM / 4;
    const int nq4 = 3 * CDIM * CDIM / 4;
    const int np4 = CDIM * CDIM / 4;

    split_bf16<<<(nx4 + 255) / 256, 256>>>(x, 0, nx4);
    split_bf16<<<(nq4 + 255) / 256, 256>>>(Wqkv, 1, nq4);
    split_bf16<<<(np4 + 255) / 256, 256>>>(Wproj, 2, np4);

    // QKV projection: (16384 x 2304 x 768); epilogue emits q/k/v bf16 splits
    gemm_tc<0><<<dim3(3 * CDIM / 128, MTOK / 128), 256, GSMEM>>>(nullptr, nullptr);

    // Flash attention; epilogue emits g_oh/g_ol bf16 splits
    attn_flash<<<dim3(BPDIM * NHEAD, SEQ / 64), 256, ATTN_SMEM>>>();

    // Output projection: (16384 x 768 x 768) + bias -> d_out
    gemm_tc<1><<<dim3(CDIM / 128, MTOK / 128), 256, GSMEM>>>(out, bproj);
}

// round 7
// speedup vs baseline: 5.7081x; 1.7189x over previous
#include <cuda_runtime.h>
#include <cuda_bf16.h>
#include <cuda_fp16.h>
#include <math.h>
#include <stdint.h>

// Problem dims
#define SEQ    512
#define NHEAD  12
#define DHEAD  64
#define CDIM   768
#define BPDIM  32              // B*P = 8*4
#define MTOK   (BPDIM * SEQ)   // 16384 tokens
#define QSCALE 0.125f          // 64^-0.5

// ---------------------------------------------------------------------------
// Device-global scratch (allocation-free per harness rules)
// ---------------------------------------------------------------------------
#define HELEMS ((size_t)BPDIM * NHEAD * SEQ * DHEAD)   // 12.58M

// q/k/v bf16 two-term splits (attention stays high-precision), q pre-scaled
__device__ __nv_bfloat16 g_qh[HELEMS];
__device__ __nv_bfloat16 g_ql[HELEMS];
__device__ __nv_bfloat16 g_kh[HELEMS];
__device__ __nv_bfloat16 g_kl[HELEMS];
__device__ __nv_bfloat16 g_vh[HELEMS];
__device__ __nv_bfloat16 g_vl[HELEMS];

// fp16 single-precision operands for the two projection GEMMs
__device__ __half g_xf[(size_t)MTOK * CDIM];
__device__ __half g_of[(size_t)MTOK * CDIM];
__device__ __half g_wqf[(size_t)3 * CDIM * CDIM];
__device__ __half g_wpf[(size_t)CDIM * CDIM];

// ---------------------------------------------------------------------------
// Base-ISA tensor helpers (mma.sync + ldmatrix + cp.async — sm_103 base target)
// ---------------------------------------------------------------------------
__device__ __forceinline__ uint32_t smem_u32(const void* p) {
    uint32_t a;
    asm("{ .reg .u64 t; cvta.to.shared.u64 t, %1; cvt.u32.u64 %0, t; }"
        : "=r"(a) : "l"(p));
    return a;
}

__device__ __forceinline__ void ldmx4(uint32_t* r, uint32_t addr) {
    asm volatile("ldmatrix.sync.aligned.m8n8.x4.shared.b16 {%0,%1,%2,%3}, [%4];"
                 : "=r"(r[0]), "=r"(r[1]), "=r"(r[2]), "=r"(r[3]) : "r"(addr));
}
__device__ __forceinline__ void ldmx4t(uint32_t* r, uint32_t addr) {
    asm volatile("ldmatrix.sync.aligned.m8n8.x4.trans.shared.b16 {%0,%1,%2,%3}, [%4];"
                 : "=r"(r[0]), "=r"(r[1]), "=r"(r[2]), "=r"(r[3]) : "r"(addr));
}

__device__ __forceinline__ void mma_bf16(float* c, const uint32_t* a,
                                         uint32_t b0, uint32_t b1) {
    asm volatile(
        "mma.sync.aligned.m16n8k16.row.col.f32.bf16.bf16.f32 "
        "{%0,%1,%2,%3}, {%4,%5,%6,%7}, {%8,%9}, {%0,%1,%2,%3};"
        : "+f"(c[0]), "+f"(c[1]), "+f"(c[2]), "+f"(c[3])
        : "r"(a[0]), "r"(a[1]), "r"(a[2]), "r"(a[3]), "r"(b0), "r"(b1));
}
__device__ __forceinline__ void mma_f16(float* c, const uint32_t* a,
                                        uint32_t b0, uint32_t b1) {
    asm volatile(
        "mma.sync.aligned.m16n8k16.row.col.f32.f16.f16.f32 "
        "{%0,%1,%2,%3}, {%4,%5,%6,%7}, {%8,%9}, {%0,%1,%2,%3};"
        : "+f"(c[0]), "+f"(c[1]), "+f"(c[2]), "+f"(c[3])
        : "r"(a[0]), "r"(a[1]), "r"(a[2]), "r"(a[3]), "r"(b0), "r"(b1));
}

__device__ __forceinline__ void cp16(uint32_t dst, const void* src) {
    asm volatile("cp.async.cg.shared.global [%0], [%1], 16;"
                 :: "r"(dst), "l"(src) : "memory");
}
#define CP_COMMIT() asm volatile("cp.async.commit_group;" ::: "memory")
#define CP_WAIT2()  asm volatile("cp.async.wait_group 2;" ::: "memory")
#define CP_WAIT1()  asm volatile("cp.async.wait_group 1;" ::: "memory")
#define CP_WAIT0()  asm volatile("cp.async.wait_group 0;" ::: "memory")

__device__ __forceinline__ void split2(float a0, float a1,
                                       uint32_t& hi, uint32_t& lo) {
    __nv_bfloat16 h0 = __float2bfloat16_rn(a0);
    __nv_bfloat16 h1 = __float2bfloat16_rn(a1);
    __nv_bfloat16 l0 = __float2bfloat16_rn(a0 - __bfloat162float(h0));
    __nv_bfloat16 l1 = __float2bfloat16_rn(a1 - __bfloat162float(h1));
    __nv_bfloat162 hh(h0, h1), ll(l0, l1);
    hi = *(uint32_t*)&hh;
    lo = *(uint32_t*)&ll;
}

// ---------------------------------------------------------------------------
// fp16 convert kernel.  sel: 0=x->g_xf  1=Wqkv->g_wqf  2=Wproj->g_wpf
// ---------------------------------------------------------------------------
__global__ void conv_f16(const float* __restrict__ in, int sel, int n4)
{
    __half* dst = (sel == 0) ? g_xf : (sel == 1) ? g_wqf : g_wpf;
    int i = blockIdx.x * blockDim.x + threadIdx.x;
    if (i >= n4) return;
    float4 v = ((const float4*)in)[i];
    __half2 a = __floats2half2_rn(v.x, v.y);
    __half2 b = __floats2half2_rn(v.z, v.w);
    ((__half2*)dst)[2 * i]     = a;
    ((__half2*)dst)[2 * i + 1] = b;
}

// ---------------------------------------------------------------------------
// Tensor-core GEMM (NT), single-product fp16, fp32 accumulate.
// CTA 128x128, BK=32, 8 warps (warp tile 64x32), 4-stage cp.async pipeline,
// XOR-swizzled 64B rows. Stage = 2 tiles x 8KB = 16KB; 4 stages = 64KB -> 2 CTA/SM.
// MODE 0: A=g_xf, B=g_wqf; epilogue bf16-splits+scatters to g_{q,k,v}{h,l}.
// MODE 1: A=g_of, B=g_wpf; +bias -> d_out (fp32).
// ---------------------------------------------------------------------------
#define GT_B    8192
#define GSTG_B  (2 * GT_B)      // 16384
#define GSMEM   (4 * GSTG_B)    // 65536
#define NCHUNK  (CDIM / 32)     // 24

template <int MODE>
__global__ __launch_bounds__(256, 2)
void gemm_tc(float* __restrict__ Cout, const float* __restrict__ bias)
{
    extern __shared__ char smem[];
    const uint32_t sb = smem_u32(smem);
    const int tid = threadIdx.x;
    const int l   = tid & 31;
    const int warp = tid >> 5;
    const int wm = warp & 1;
    const int wn = warp >> 1;
    const int bn = blockIdx.x, bm = blockIdx.y;
    const int K = CDIM;

    const __half* srcs[2] = {
        ((MODE == 0) ? g_xf : g_of) + (size_t)(bm * 128) * K,
        ((MODE == 0) ? g_wqf : g_wpf) + (size_t)(bn * 128) * K };

    const int lrow  = l & 15;
    const int lhalf = l >> 4;

    float acc[4][4][4];
#pragma unroll
    for (int i = 0; i < 4; i++)
#pragma unroll
        for (int j = 0; j < 4; j++)
#pragma unroll
            for (int q = 0; q < 4; q++) acc[i][j][q] = 0.f;

#define LOAD_CHUNK(c, st)                                                      \
    do {                                                                       \
        _Pragma("unroll")                                                      \
        for (int j = 0; j < 4; j++) {                                          \
            const int i = tid + j * 256;                                       \
            const int t = i >> 9, r = (i >> 2) & 127, u = i & 3;               \
            const uint32_t dst = sb + (st) * GSTG_B + t * GT_B + r * 64        \
                               + ((u ^ ((r >> 1) & 3)) << 4);                  \
            cp16(dst, srcs[t] + (size_t)r * K + (c) * 32 + u * 8);             \
        }                                                                      \
        CP_COMMIT();                                                           \
    } while (0)

    LOAD_CHUNK(0, 0);
    LOAD_CHUNK(1, 1);
    LOAD_CHUNK(2, 2);

    for (int c = 0; c < NCHUNK; c++) {
        CP_WAIT2();
        __syncthreads();
        if (c + 3 < NCHUNK) {
            LOAD_CHUNK(c + 3, (c + 3) & 3);
        } else {
            CP_COMMIT();
        }

        const uint32_t stg = sb + (c & 3) * GSTG_B;
#pragma unroll
        for (int s = 0; s < 2; s++) {
            const int slot = s * 2 + lhalf;
            uint32_t bf[8];
#pragma unroll
            for (int np = 0; np < 2; np++) {
                const int R = wn * 32 + np * 16 + lrow;
                const uint32_t off = R * 64 + ((slot ^ ((R >> 1) & 3)) << 4);
                ldmx4(&bf[np * 4], stg + GT_B + off);
            }
#pragma unroll
            for (int mt = 0; mt < 4; mt++) {
                const int R = wm * 64 + mt * 16 + lrow;
                const uint32_t off = R * 64 + ((slot ^ ((R >> 1) & 3)) << 4);
                uint32_t af[4];
                ldmx4(af, stg + off);
#pragma unroll
                for (int nt = 0; nt < 4; nt++) {
                    const int np = nt >> 1, q = nt & 1;
                    mma_f16(acc[mt][nt], af, bf[np * 4 + q], bf[np * 4 + q + 2]);
                }
            }
        }
    }
#undef LOAD_CHUNK

#pragma unroll
    for (int mt = 0; mt < 4; mt++) {
#pragma unroll
        for (int nt = 0; nt < 4; nt++) {
            const int m0 = bm * 128 + wm * 64 + mt * 16 + (l >> 2);
            const int d  = bn * 128 + wn * 32 + nt * 8 + 2 * (l & 3);
#pragma unroll
            for (int half = 0; half < 2; half++) {
                const int m = m0 + half * 8;
                const float v0 = acc[mt][nt][half * 2 + 0];
                const float v1 = acc[mt][nt][half * 2 + 1];
                if (MODE == 0) {
                    const int bp = m >> 9;
                    const int n  = m & (SEQ - 1);
                    const int ss  = d / CDIM;
                    const int rem = d - ss * CDIM;
                    const int h   = rem >> 6;
                    const int hd  = rem & 63;
                    const size_t base = ((size_t)(bp * NHEAD + h) * SEQ + n) * DHEAD + hd;
                    const float sc = (ss == 0) ? QSCALE : 1.0f;
                    uint32_t hi, lo;
                    split2(v0 * sc, v1 * sc, hi, lo);
                    __nv_bfloat16* dh = (ss == 0) ? g_qh : (ss == 1) ? g_kh : g_vh;
                    __nv_bfloat16* dl = (ss == 0) ? g_ql : (ss == 1) ? g_kl : g_vl;
                    *(uint32_t*)(dh + base) = hi;
                    *(uint32_t*)(dl + base) = lo;
                } else {
                    float2 bv = *(const float2*)(bias + d);
                    *(float2*)(Cout + (size_t)m * CDIM + d) =
                        make_float2(v0 + bv.x, v1 + bv.y);
                }
            }
        }
    }
}

// ---------------------------------------------------------------------------
// Flash attention (online softmax, register-resident S and O) — unchanged
// math from round 6 except the epilogue now emits fp16 g_of.
// ---------------------------------------------------------------------------
#define AT_STRIDE 144
#define AT_TILE   (64 * AT_STRIDE)          // 9216
#define ASM_Q     0
#define ASM_KV    (2 * AT_TILE)             // 18432
#define ASM_STG   (4 * AT_TILE)             // 36864 per stage (Kh,Kl,Vh,Vl)
#define ASM_MAX   (ASM_KV + 2 * ASM_STG)    // 92160
#define ASM_SUM   (ASM_MAX + 512)           // 92672
#define ASM_O     ASM_KV                    // overlay after last chunk
#define AO_STR    66
#define ATTN_SMEM (ASM_SUM + 512)           // 93184

__global__ __launch_bounds__(256, 2)
void attn_flash()
{
    extern __shared__ char sm[];
    const uint32_t sb = smem_u32(sm);
    float* smax = (float*)(sm + ASM_MAX);   // [64][2]
    float* ssum = (float*)(sm + ASM_SUM);   // [64][2]
    float* sO   = (float*)(sm + ASM_O);     // [2][64][66]

    const int tid = threadIdx.x, l = tid & 31, w = tid >> 5;
    const int mw = w & 3, nw = w >> 2;
    const int bph = blockIdx.x, qt = blockIdx.y;
    const size_t hoff = (size_t)bph * SEQ * DHEAD;
    const __nv_bfloat16* qh = g_qh + hoff + (size_t)qt * 64 * DHEAD;
    const __nv_bfloat16* ql = g_ql + hoff + (size_t)qt * 64 * DHEAD;
    const __nv_bfloat16* asrc[4] = { g_kh + hoff, g_kl + hoff,
                                     g_vh + hoff, g_vl + hoff };

    const int lrow  = l & 15;
    const int lcolb = (l >> 4) << 4;
    const int r0    = mw * 16 + (l >> 2);

    for (int i = tid; i < 1024; i += 256) {
        const int t = i >> 9, r = (i >> 3) & 63, u = i & 7;
        const __nv_bfloat16* src = (t == 0) ? qh : ql;
        *(uint4*)(sm + ASM_Q + t * AT_TILE + r * AT_STRIDE + u * 16) =
            *(const uint4*)(src + r * 64 + u * 8);
    }

#define ALOAD(c, st)                                                           \
    do {                                                                       \
        _Pragma("unroll")                                                      \
        for (int j = 0; j < 8; j++) {                                          \
            const int i = tid + j * 256;                                       \
            const int t = i >> 9, r = (i >> 3) & 63, u = i & 7;                \
            cp16(sb + ASM_KV + (st) * ASM_STG + t * AT_TILE + r * AT_STRIDE    \
                     + u * 16,                                                 \
                 asrc[t] + (size_t)(c) * 64 * 64 + r * 64 + u * 8);            \
        }                                                                      \
        CP_COMMIT();                                                           \
    } while (0)

    ALOAD(0, 0);

    float accO[8][4];
#pragma unroll
    for (int i = 0; i < 8; i++)
#pragma unroll
        for (int q = 0; q < 4; q++) accO[i][q] = 0.f;
    float mrun0 = -1e30f, mrun1 = -1e30f;
    float lsum0 = 0.f, lsum1 = 0.f;

    for (int kc = 0; kc < 8; kc++) {
        if (kc < 7) { ALOAD(kc + 1, (kc + 1) & 1); CP_WAIT1(); }
        else        { CP_WAIT0(); }
        __syncthreads();

        const uint32_t stg = sb + ASM_KV + (kc & 1) * ASM_STG;

        float accS[4][4] = {};
#pragma unroll
        for (int ks = 0; ks < 4; ks++) {
            uint32_t qfh[4], qfl[4];
            const uint32_t qro = (mw * 16 + lrow) * AT_STRIDE + ks * 32 + lcolb;
            ldmx4(qfh, sb + ASM_Q + qro);
            ldmx4(qfl, sb + ASM_Q + AT_TILE + qro);
            uint32_t kbh[8], kbl[8];
#pragma unroll
            for (int np = 0; np < 2; np++) {
                const uint32_t off = (nw * 32 + np * 16 + lrow) * AT_STRIDE
                                   + ks * 32 + lcolb;
                ldmx4(&kbh[np * 4], stg + off);
                ldmx4(&kbl[np * 4], stg + AT_TILE + off);
            }
#pragma unroll
            for (int nt = 0; nt < 4; nt++) {
                const int np = nt >> 1, q = nt & 1;
                mma_bf16(accS[nt], qfh, kbh[np * 4 + q], kbh[np * 4 + q + 2]);
                mma_bf16(accS[nt], qfh, kbl[np * 4 + q], kbl[np * 4 + q + 2]);
                mma_bf16(accS[nt], qfl, kbh[np * 4 + q], kbh[np * 4 + q + 2]);
            }
        }

        float ml0 = -1e30f, ml1 = -1e30f;
#pragma unroll
        for (int nt = 0; nt < 4; nt++) {
            ml0 = fmaxf(ml0, fmaxf(accS[nt][0], accS[nt][1]));
            ml1 = fmaxf(ml1, fmaxf(accS[nt][2], accS[nt][3]));
        }
        ml0 = fmaxf(ml0, __shfl_xor_sync(0xffffffffu, ml0, 1));
        ml0 = fmaxf(ml0, __shfl_xor_sync(0xffffffffu, ml0, 2));
        ml1 = fmaxf(ml1, __shfl_xor_sync(0xffffffffu, ml1, 1));
        ml1 = fmaxf(ml1, __shfl_xor_sync(0xffffffffu, ml1, 2));
        if ((l & 3) == 0) {
            smax[r0 * 2 + nw]       = ml0;
            smax[(r0 + 8) * 2 + nw] = ml1;
        }
        __syncthreads();
        const float mc0 = fmaxf(smax[r0 * 2], smax[r0 * 2 + 1]);
        const float mc1 = fmaxf(smax[(r0 + 8) * 2], smax[(r0 + 8) * 2 + 1]);
        const float mn0 = fmaxf(mrun0, mc0), mn1 = fmaxf(mrun1, mc1);
        const float sc0 = __expf(mrun0 - mn0), sc1 = __expf(mrun1 - mn1);
        mrun0 = mn0; mrun1 = mn1;
        lsum0 *= sc0; lsum1 *= sc1;
#pragma unroll
        for (int nt = 0; nt < 8; nt++) {
            accO[nt][0] *= sc0; accO[nt][1] *= sc0;
            accO[nt][2] *= sc1; accO[nt][3] *= sc1;
        }

        uint32_t Ph[2][4], Pl[2][4];
        float ps0 = 0.f, ps1 = 0.f;
#pragma unroll
        for (int kb = 0; kb < 2; kb++) {
            const float p00 = __expf(accS[2 * kb][0] - mn0);
            const float p01 = __expf(accS[2 * kb][1] - mn0);
            const float p10 = __expf(accS[2 * kb][2] - mn1);
            const float p11 = __expf(accS[2 * kb][3] - mn1);
            const float p20 = __expf(accS[2 * kb + 1][0] - mn0);
            const float p21 = __expf(accS[2 * kb + 1][1] - mn0);
            const float p30 = __expf(accS[2 * kb + 1][2] - mn1);
            const float p31 = __expf(accS[2 * kb + 1][3] - mn1);
            ps0 += p00 + p01 + p20 + p21;
            ps1 += p10 + p11 + p30 + p31;
            split2(p00, p01, Ph[kb][0], Pl[kb][0]);
            split2(p10, p11, Ph[kb][1], Pl[kb][1]);
            split2(p20, p21, Ph[kb][2], Pl[kb][2]);
            split2(p30, p31, Ph[kb][3], Pl[kb][3]);
        }
        ps0 += __shfl_xor_sync(0xffffffffu, ps0, 1);
        ps0 += __shfl_xor_sync(0xffffffffu, ps0, 2);
        ps1 += __shfl_xor_sync(0xffffffffu, ps1, 1);
        ps1 += __shfl_xor_sync(0xffffffffu, ps1, 2);
        lsum0 += ps0; lsum1 += ps1;

#pragma unroll
        for (int kb = 0; kb < 2; kb++) {
#pragma unroll
            for (int np = 0; np < 4; np++) {
                uint32_t vbh[4], vbl[4];
                const uint32_t ad =
                    (nw * 32 + kb * 16 + (l & 7) + (((l >> 3) & 1) << 3)) * AT_STRIDE
                    + (np * 16 + ((l >> 4) << 3)) * 2;
                ldmx4t(vbh, stg + 2 * AT_TILE + ad);
                ldmx4t(vbl, stg + 3 * AT_TILE + ad);
#pragma unroll
                for (int q = 0; q < 2; q++) {
                    const int nt = np * 2 + q;
                    mma_bf16(accO[nt], Ph[kb], vbh[2 * q], vbh[2 * q + 1]);
                    mma_bf16(accO[nt], Ph[kb], vbl[2 * q], vbl[2 * q + 1]);
                    mma_bf16(accO[nt], Pl[kb], vbh[2 * q], vbh[2 * q + 1]);
                }
            }
        }
        __syncthreads();
    }
#undef ALOAD

    if ((l & 3) == 0) {
        ssum[r0 * 2 + nw]       = lsum0;
        ssum[(r0 + 8) * 2 + nw] = lsum1;
    }
#pragma unroll
    for (int nt = 0; nt < 8; nt++) {
        const int col = nt * 8 + 2 * (l & 3);
        *(float2*)&sO[(nw * 64 + r0) * AO_STR + col] =
            make_float2(accO[nt][0], accO[nt][1]);
        *(float2*)&sO[(nw * 64 + r0 + 8) * AO_STR + col] =
            make_float2(accO[nt][2], accO[nt][3]);
    }
    __syncthreads();

    const int h  = bph % NHEAD;
    const int bp = bph / NHEAD;
    for (int i = tid; i < 2048; i += 256) {
        const int r = i >> 5, c = (i & 31) * 2;
        const float inv = 1.0f / (ssum[r * 2] + ssum[r * 2 + 1]);
        const float o0 = (sO[r * AO_STR + c]     + sO[(64 + r) * AO_STR + c])     * inv;
        const float o1 = (sO[r * AO_STR + c + 1] + sO[(64 + r) * AO_STR + c + 1]) * inv;
        __half2 hv = __floats2half2_rn(o0, o1);
        const size_t grow = ((size_t)bp * SEQ + qt * 64 + r) * CDIM + h * DHEAD + c;
        *(__half2*)(g_of + grow) = hv;
    }
}

// ---------------------------------------------------------------------------
extern "C" void kernel_launch(void* const* d_in, const int* in_sizes, int n_in,
                              void* d_out, int out_size)
{
    const float* x     = (const float*)d_in[0];  // (8,4,512,768)
    const float* Wqkv  = (const float*)d_in[1];  // (2304,768)
    const float* Wproj = (const float*)d_in[2];  // (768,768)
    const float* bproj = (const float*)d_in[3];  // (768,)
    float* out = (float*)d_out;

    cudaFuncSetAttribute(gemm_tc<0>, cudaFuncAttributeMaxDynamicSharedMemorySize, GSMEM);
    cudaFuncSetAttribute(gemm_tc<1>, cudaFuncAttributeMaxDynamicSharedMemorySize, GSMEM);
    cudaFuncSetAttribute(attn_flash, cudaFuncAttributeMaxDynamicSharedMemorySize, ATTN_SMEM);

    const int nx4 = MTOK * CDIM / 4;
    const int nq4 = 3 * CDIM * CDIM / 4;
    const int np4 = CDIM * CDIM / 4;

    conv_f16<<<(nx4 + 255) / 256, 256>>>(x, 0, nx4);
    conv_f16<<<(nq4 + 255) / 256, 256>>>(Wqkv, 1, nq4);
    conv_f16<<<(np4 + 255) / 256, 256>>>(Wproj, 2, np4);

    // QKV projection (fp16 single product); epilogue emits q/k/v bf16 splits
    gemm_tc<0><<<dim3(3 * CDIM / 128, MTOK / 128), 256, GSMEM>>>(nullptr, nullptr);

    // Flash attention (bf16 3-product); epilogue emits g_of fp16
    attn_flash<<<dim3(BPDIM * NHEAD, SEQ / 64), 256, ATTN_SMEM>>>();

    // Output projection (fp16 single product) + bias -> d_out
    gemm_tc<1><<<dim3(CDIM / 128, MTOK / 128), 256, GSMEM>>>(out, bproj);
}

// round 8
// speedup vs baseline: 7.0935x; 1.2427x over previous
#include <cuda_runtime.h>
#include <cuda_bf16.h>
#include <cuda_fp16.h>
#include <math.h>
#include <stdint.h>

// Problem dims
#define SEQ    512
#define NHEAD  12
#define DHEAD  64
#define CDIM   768
#define BPDIM  32              // B*P = 8*4
#define MTOK   (BPDIM * SEQ)   // 16384 tokens
#define QSCALE 0.125f          // 64^-0.5

// ---------------------------------------------------------------------------
// Device-global scratch (allocation-free per harness rules)
// ---------------------------------------------------------------------------
#define HELEMS ((size_t)BPDIM * NHEAD * SEQ * DHEAD)   // 12.58M

// attention operands: q fp16 two-term split (pre-scaled), k/v single fp16
__device__ __half g_qh[HELEMS];
__device__ __half g_ql[HELEMS];
__device__ __half g_kf[HELEMS];
__device__ __half g_vf[HELEMS];

// fp16 operands for the two projection GEMMs
__device__ __half g_xf[(size_t)MTOK * CDIM];
__device__ __half g_of[(size_t)MTOK * CDIM];
__device__ __half g_wqf[(size_t)3 * CDIM * CDIM];
__device__ __half g_wpf[(size_t)CDIM * CDIM];

// ---------------------------------------------------------------------------
// Base-ISA tensor helpers (mma.sync + ldmatrix + cp.async — sm_103 base target)
// ---------------------------------------------------------------------------
__device__ __forceinline__ uint32_t smem_u32(const void* p) {
    uint32_t a;
    asm("{ .reg .u64 t; cvta.to.shared.u64 t, %1; cvt.u32.u64 %0, t; }"
        : "=r"(a) : "l"(p));
    return a;
}

__device__ __forceinline__ void ldmx4(uint32_t* r, uint32_t addr) {
    asm volatile("ldmatrix.sync.aligned.m8n8.x4.shared.b16 {%0,%1,%2,%3}, [%4];"
                 : "=r"(r[0]), "=r"(r[1]), "=r"(r[2]), "=r"(r[3]) : "r"(addr));
}
__device__ __forceinline__ void ldmx4t(uint32_t* r, uint32_t addr) {
    asm volatile("ldmatrix.sync.aligned.m8n8.x4.trans.shared.b16 {%0,%1,%2,%3}, [%4];"
                 : "=r"(r[0]), "=r"(r[1]), "=r"(r[2]), "=r"(r[3]) : "r"(addr));
}

__device__ __forceinline__ void mma_f16(float* c, const uint32_t* a,
                                        uint32_t b0, uint32_t b1) {
    asm volatile(
        "mma.sync.aligned.m16n8k16.row.col.f32.f16.f16.f32 "
        "{%0,%1,%2,%3}, {%4,%5,%6,%7}, {%8,%9}, {%0,%1,%2,%3};"
        : "+f"(c[0]), "+f"(c[1]), "+f"(c[2]), "+f"(c[3])
        : "r"(a[0]), "r"(a[1]), "r"(a[2]), "r"(a[3]), "r"(b0), "r"(b1));
}

__device__ __forceinline__ void cp16(uint32_t dst, const void* src) {
    asm volatile("cp.async.cg.shared.global [%0], [%1], 16;"
                 :: "r"(dst), "l"(src) : "memory");
}
#define CP_COMMIT() asm volatile("cp.async.commit_group;" ::: "memory")
#define CP_WAIT1()  asm volatile("cp.async.wait_group 1;" ::: "memory")
#define CP_WAIT0()  asm volatile("cp.async.wait_group 0;" ::: "memory")

// fp16 two-term split: hi = fp16(x), lo = fp16(x - hi)  (exact to ~2^-22)
__device__ __forceinline__ void split2h(float a0, float a1,
                                        uint32_t& hi, uint32_t& lo) {
    __half h0 = __float2half_rn(a0);
    __half h1 = __float2half_rn(a1);
    __half l0 = __float2half_rn(a0 - __half2float(h0));
    __half l1 = __float2half_rn(a1 - __half2float(h1));
    __half2 hh(h0, h1), ll(l0, l1);
    hi = *(uint32_t*)&hh;
    lo = *(uint32_t*)&ll;
}

// ---------------------------------------------------------------------------
// fp16 convert kernel.  sel: 0=x->g_xf  1=Wqkv->g_wqf  2=Wproj->g_wpf
// ---------------------------------------------------------------------------
__global__ void conv_f16(const float* __restrict__ in, int sel, int n4)
{
    __half* dst = (sel == 0) ? g_xf : (sel == 1) ? g_wqf : g_wpf;
    int i = blockIdx.x * blockDim.x + threadIdx.x;
    if (i >= n4) return;
    float4 v = ((const float4*)in)[i];
    ((__half2*)dst)[2 * i]     = __floats2half2_rn(v.x, v.y);
    ((__half2*)dst)[2 * i + 1] = __floats2half2_rn(v.z, v.w);
}

// ---------------------------------------------------------------------------
// Tensor-core GEMM (NT), single-product fp16, fp32 accumulate.
// CTA 128x128, BK=64, 8 warps (warp tile 64x32), 3-stage cp.async pipeline,
// XOR-swizzled 128B rows (8 slots). Stage = 2 x 16KB = 32KB; 3 stages = 96KB.
// MODE 0: A=g_xf, B=g_wqf; epilogue: q fp16-split, k/v single fp16.
// MODE 1: A=g_of, B=g_wpf; +bias -> d_out (fp32).
// ---------------------------------------------------------------------------
#define GT_B    16384
#define GSTG_B  (2 * GT_B)      // 32768
#define GSMEM   (3 * GSTG_B)    // 98304
#define NCHUNK  (CDIM / 64)     // 12

template <int MODE>
__global__ __launch_bounds__(256, 2)
void gemm_tc(float* __restrict__ Cout, const float* __restrict__ bias)
{
    extern __shared__ char smem[];
    const uint32_t sb = smem_u32(smem);
    const int tid = threadIdx.x;
    const int l   = tid & 31;
    const int warp = tid >> 5;
    const int wm = warp & 1;
    const int wn = warp >> 1;
    const int bn = blockIdx.x, bm = blockIdx.y;
    const int K = CDIM;

    const __half* srcs[2] = {
        ((MODE == 0) ? g_xf : g_of) + (size_t)(bm * 128) * K,
        ((MODE == 0) ? g_wqf : g_wpf) + (size_t)(bn * 128) * K };

    const int lrow  = l & 15;
    const int lhalf = l >> 4;

    float acc[4][4][4];
#pragma unroll
    for (int i = 0; i < 4; i++)
#pragma unroll
        for (int j = 0; j < 4; j++)
#pragma unroll
            for (int q = 0; q < 4; q++) acc[i][j][q] = 0.f;

#define LOAD_CHUNK(c, st)                                                      \
    do {                                                                       \
        _Pragma("unroll")                                                      \
        for (int j = 0; j < 8; j++) {                                          \
            const int i = tid + j * 256;                                       \
            const int t = i >> 10, r = (i >> 3) & 127, u = i & 7;              \
            const uint32_t dst = sb + (st) * GSTG_B + t * GT_B + r * 128       \
                               + ((u ^ (r & 7)) << 4);                         \
            cp16(dst, srcs[t] + (size_t)r * K + (c) * 64 + u * 8);             \
        }                                                                      \
        CP_COMMIT();                                                           \
    } while (0)

    LOAD_CHUNK(0, 0);
    LOAD_CHUNK(1, 1);

    for (int c = 0; c < NCHUNK; c++) {
        CP_WAIT1();
        __syncthreads();
        if (c + 2 < NCHUNK) {
            LOAD_CHUNK(c + 2, (c + 2) % 3);
        } else {
            CP_COMMIT();
        }

        const uint32_t stg = sb + (c % 3) * GSTG_B;
#pragma unroll
        for (int s = 0; s < 4; s++) {
            const int slot = s * 2 + lhalf;
            uint32_t bf[8];
#pragma unroll
            for (int np = 0; np < 2; np++) {
                const int R = wn * 32 + np * 16 + lrow;
                const uint32_t off = R * 128 + ((slot ^ (R & 7)) << 4);
                ldmx4(&bf[np * 4], stg + GT_B + off);
            }
#pragma unroll
            for (int mt = 0; mt < 4; mt++) {
                const int R = wm * 64 + mt * 16 + lrow;
                const uint32_t off = R * 128 + ((slot ^ (R & 7)) << 4);
                uint32_t af[4];
                ldmx4(af, stg + off);
#pragma unroll
                for (int nt = 0; nt < 4; nt++) {
                    const int np = nt >> 1, q = nt & 1;
                    mma_f16(acc[mt][nt], af, bf[np * 4 + q], bf[np * 4 + q + 2]);
                }
            }
        }
    }
#undef LOAD_CHUNK

#pragma unroll
    for (int mt = 0; mt < 4; mt++) {
#pragma unroll
        for (int nt = 0; nt < 4; nt++) {
            const int m0 = bm * 128 + wm * 64 + mt * 16 + (l >> 2);
            const int d  = bn * 128 + wn * 32 + nt * 8 + 2 * (l & 3);
#pragma unroll
            for (int half = 0; half < 2; half++) {
                const int m = m0 + half * 8;
                const float v0 = acc[mt][nt][half * 2 + 0];
                const float v1 = acc[mt][nt][half * 2 + 1];
                if (MODE == 0) {
                    const int bp = m >> 9;
                    const int n  = m & (SEQ - 1);
                    const int ss  = d / CDIM;
                    const int rem = d - ss * CDIM;
                    const int h   = rem >> 6;
                    const int hd  = rem & 63;
                    const size_t base = ((size_t)(bp * NHEAD + h) * SEQ + n) * DHEAD + hd;
                    if (ss == 0) {
                        uint32_t hi, lo;
                        split2h(v0 * QSCALE, v1 * QSCALE, hi, lo);
                        *(uint32_t*)(g_qh + base) = hi;
                        *(uint32_t*)(g_ql + base) = lo;
                    } else {
                        __half2 hv = __floats2half2_rn(v0, v1);
                        *(__half2*)(((ss == 1) ? g_kf : g_vf) + base) = hv;
                    }
                } else {
                    float2 bv = *(const float2*)(bias + d);
                    *(float2*)(Cout + (size_t)m * CDIM + d) =
                        make_float2(v0 + bv.x, v1 + bv.y);
                }
            }
        }
    }
}

// ---------------------------------------------------------------------------
// Flash attention (online softmax, register-resident S and O).
// 2-product asymmetric precision: fp16-split Q x single-fp16 K (QK^T),
// fp16-split P x single-fp16 V (PV). K/V single tiles halve SMEM traffic.
// ---------------------------------------------------------------------------
#define AT_STRIDE 144
#define AT_TILE   (64 * AT_STRIDE)          // 9216
#define ASM_Q     0                         // Qh, Ql: 2 tiles
#define ASM_KV    (2 * AT_TILE)             // 18432
#define ASM_STG   (2 * AT_TILE)             // 18432 per stage (K, V)
#define ASM_MAX   (ASM_KV + 2 * ASM_STG)    // 55296
#define ASM_SUM   (ASM_MAX + 512)           // 55808
#define ASM_O     ASM_KV                    // overlay after last chunk (33792B)
#define AO_STR    66
#define ATTN_SMEM (ASM_SUM + 512)           // 56320

__global__ __launch_bounds__(256, 2)
void attn_flash()
{
    extern __shared__ char sm[];
    const uint32_t sb = smem_u32(sm);
    float* smax = (float*)(sm + ASM_MAX);   // [64][2]
    float* ssum = (float*)(sm + ASM_SUM);   // [64][2]
    float* sO   = (float*)(sm + ASM_O);     // [2][64][66]

    const int tid = threadIdx.x, l = tid & 31, w = tid >> 5;
    const int mw = w & 3, nw = w >> 2;
    const int bph = blockIdx.x, qt = blockIdx.y;
    const size_t hoff = (size_t)bph * SEQ * DHEAD;
    const __half* qh = g_qh + hoff + (size_t)qt * 64 * DHEAD;
    const __half* ql = g_ql + hoff + (size_t)qt * 64 * DHEAD;
    const __half* asrc[2] = { g_kf + hoff, g_vf + hoff };

    const int lrow  = l & 15;
    const int lcolb = (l >> 4) << 4;
    const int r0    = mw * 16 + (l >> 2);

    // Q tiles (h,l) one-time plain stores
    for (int i = tid; i < 1024; i += 256) {
        const int t = i >> 9, r = (i >> 3) & 63, u = i & 7;
        const __half* src = (t == 0) ? qh : ql;
        *(uint4*)(sm + ASM_Q + t * AT_TILE + r * AT_STRIDE + u * 16) =
            *(const uint4*)(src + r * 64 + u * 8);
    }

#define ALOAD(c, st)                                                           \
    do {                                                                       \
        _Pragma("unroll")                                                      \
        for (int j = 0; j < 4; j++) {                                          \
            const int i = tid + j * 256;                                       \
            const int t = i >> 9, r = (i >> 3) & 63, u = i & 7;                \
            cp16(sb + ASM_KV + (st) * ASM_STG + t * AT_TILE + r * AT_STRIDE    \
                     + u * 16,                                                 \
                 asrc[t] + (size_t)(c) * 64 * 64 + r * 64 + u * 8);            \
        }                                                                      \
        CP_COMMIT();                                                           \
    } while (0)

    ALOAD(0, 0);

    float accO[8][4];
#pragma unroll
    for (int i = 0; i < 8; i++)
#pragma unroll
        for (int q = 0; q < 4; q++) accO[i][q] = 0.f;
    float mrun0 = -1e30f, mrun1 = -1e30f;
    float lsum0 = 0.f, lsum1 = 0.f;

    for (int kc = 0; kc < 8; kc++) {
        if (kc < 7) { ALOAD(kc + 1, (kc + 1) & 1); CP_WAIT1(); }
        else        { CP_WAIT0(); }
        __syncthreads();

        const uint32_t stg = sb + ASM_KV + (kc & 1) * ASM_STG;

        // ---- QK^T: 2 products (Qh*K + Ql*K) ----
        float accS[4][4] = {};
#pragma unroll
        for (int ks = 0; ks < 4; ks++) {
            uint32_t qfh[4], qfl[4];
            const uint32_t qro = (mw * 16 + lrow) * AT_STRIDE + ks * 32 + lcolb;
            ldmx4(qfh, sb + ASM_Q + qro);
            ldmx4(qfl, sb + ASM_Q + AT_TILE + qro);
            uint32_t kb[8];
#pragma unroll
            for (int np = 0; np < 2; np++) {
                const uint32_t off = (nw * 32 + np * 16 + lrow) * AT_STRIDE
                                   + ks * 32 + lcolb;
                ldmx4(&kb[np * 4], stg + off);
            }
#pragma unroll
            for (int nt = 0; nt < 4; nt++) {
                const int np = nt >> 1, q = nt & 1;
                mma_f16(accS[nt], qfh, kb[np * 4 + q], kb[np * 4 + q + 2]);
                mma_f16(accS[nt], qfl, kb[np * 4 + q], kb[np * 4 + q + 2]);
            }
        }

        // ---- online softmax (chunk max, one cross-warp exchange) ----
        float ml0 = -1e30f, ml1 = -1e30f;
#pragma unroll
        for (int nt = 0; nt < 4; nt++) {
            ml0 = fmaxf(ml0, fmaxf(accS[nt][0], accS[nt][1]));
            ml1 = fmaxf(ml1, fmaxf(accS[nt][2], accS[nt][3]));
        }
        ml0 = fmaxf(ml0, __shfl_xor_sync(0xffffffffu, ml0, 1));
        ml0 = fmaxf(ml0, __shfl_xor_sync(0xffffffffu, ml0, 2));
        ml1 = fmaxf(ml1, __shfl_xor_sync(0xffffffffu, ml1, 1));
        ml1 = fmaxf(ml1, __shfl_xor_sync(0xffffffffu, ml1, 2));
        if ((l & 3) == 0) {
            smax[r0 * 2 + nw]       = ml0;
            smax[(r0 + 8) * 2 + nw] = ml1;
        }
        __syncthreads();
        const float mc0 = fmaxf(smax[r0 * 2], smax[r0 * 2 + 1]);
        const float mc1 = fmaxf(smax[(r0 + 8) * 2], smax[(r0 + 8) * 2 + 1]);
        const float mn0 = fmaxf(mrun0, mc0), mn1 = fmaxf(mrun1, mc1);
        const float sc0 = __expf(mrun0 - mn0), sc1 = __expf(mrun1 - mn1);
        mrun0 = mn0; mrun1 = mn1;
        lsum0 *= sc0; lsum1 *= sc1;
#pragma unroll
        for (int nt = 0; nt < 8; nt++) {
            accO[nt][0] *= sc0; accO[nt][1] *= sc0;
            accO[nt][2] *= sc1; accO[nt][3] *= sc1;
        }

        // ---- P = exp(S - m) -> fp16-split A-frags ----
        uint32_t Ph[2][4], Pl[2][4];
        float ps0 = 0.f, ps1 = 0.f;
#pragma unroll
        for (int kb2 = 0; kb2 < 2; kb2++) {
            const float p00 = __expf(accS[2 * kb2][0] - mn0);
            const float p01 = __expf(accS[2 * kb2][1] - mn0);
            const float p10 = __expf(accS[2 * kb2][2] - mn1);
            const float p11 = __expf(accS[2 * kb2][3] - mn1);
            const float p20 = __expf(accS[2 * kb2 + 1][0] - mn0);
            const float p21 = __expf(accS[2 * kb2 + 1][1] - mn0);
            const float p30 = __expf(accS[2 * kb2 + 1][2] - mn1);
            const float p31 = __expf(accS[2 * kb2 + 1][3] - mn1);
            ps0 += p00 + p01 + p20 + p21;
            ps1 += p10 + p11 + p30 + p31;
            split2h(p00, p01, Ph[kb2][0], Pl[kb2][0]);
            split2h(p10, p11, Ph[kb2][1], Pl[kb2][1]);
            split2h(p20, p21, Ph[kb2][2], Pl[kb2][2]);
            split2h(p30, p31, Ph[kb2][3], Pl[kb2][3]);
        }
        ps0 += __shfl_xor_sync(0xffffffffu, ps0, 1);
        ps0 += __shfl_xor_sync(0xffffffffu, ps0, 2);
        ps1 += __shfl_xor_sync(0xffffffffu, ps1, 1);
        ps1 += __shfl_xor_sync(0xffffffffu, ps1, 2);
        lsum0 += ps0; lsum1 += ps1;

        // ---- PV: 2 products (Ph*V + Pl*V) ----
#pragma unroll
        for (int kb2 = 0; kb2 < 2; kb2++) {
#pragma unroll
            for (int np = 0; np < 4; np++) {
                uint32_t vb[4];
                const uint32_t ad =
                    (nw * 32 + kb2 * 16 + (l & 7) + (((l >> 3) & 1) << 3)) * AT_STRIDE
                    + (np * 16 + ((l >> 4) << 3)) * 2;
                ldmx4t(vb, stg + AT_TILE + ad);
#pragma unroll
                for (int q = 0; q < 2; q++) {
                    const int nt = np * 2 + q;
                    mma_f16(accO[nt], Ph[kb2], vb[2 * q], vb[2 * q + 1]);
                    mma_f16(accO[nt], Pl[kb2], vb[2 * q], vb[2 * q + 1]);
                }
            }
        }
        __syncthreads();   // stage reuse fence
    }
#undef ALOAD

    // ---- combine the two key-halves + normalize + fp16 store ----
    if ((l & 3) == 0) {
        ssum[r0 * 2 + nw]       = lsum0;
        ssum[(r0 + 8) * 2 + nw] = lsum1;
    }
#pragma unroll
    for (int nt = 0; nt < 8; nt++) {
        const int col = nt * 8 + 2 * (l & 3);
        *(float2*)&sO[(nw * 64 + r0) * AO_STR + col] =
            make_float2(accO[nt][0], accO[nt][1]);
        *(float2*)&sO[(nw * 64 + r0 + 8) * AO_STR + col] =
            make_float2(accO[nt][2], accO[nt][3]);
    }
    __syncthreads();

    const int h  = bph % NHEAD;
    const int bp = bph / NHEAD;
    for (int i = tid; i < 2048; i += 256) {
        const int r = i >> 5, c = (i & 31) * 2;
        const float inv = 1.0f / (ssum[r * 2] + ssum[r * 2 + 1]);
        const float o0 = (sO[r * AO_STR + c]     + sO[(64 + r) * AO_STR + c])     * inv;
        const float o1 = (sO[r * AO_STR + c + 1] + sO[(64 + r) * AO_STR + c + 1]) * inv;
        __half2 hv = __floats2half2_rn(o0, o1);
        const size_t grow = ((size_t)bp * SEQ + qt * 64 + r) * CDIM + h * DHEAD + c;
        *(__half2*)(g_of + grow) = hv;
    }
}

// ---------------------------------------------------------------------------
extern "C" void kernel_launch(void* const* d_in, const int* in_sizes, int n_in,
                              void* d_out, int out_size)
{
    const float* x     = (const float*)d_in[0];  // (8,4,512,768)
    const float* Wqkv  = (const float*)d_in[1];  // (2304,768)
    const float* Wproj = (const float*)d_in[2];  // (768,768)
    const float* bproj = (const float*)d_in[3];  // (768,)
    float* out = (float*)d_out;

    cudaFuncSetAttribute(gemm_tc<0>, cudaFuncAttributeMaxDynamicSharedMemorySize, GSMEM);
    cudaFuncSetAttribute(gemm_tc<1>, cudaFuncAttributeMaxDynamicSharedMemorySize, GSMEM);
    cudaFuncSetAttribute(attn_flash, cudaFuncAttributeMaxDynamicSharedMemorySize, ATTN_SMEM);

    const int nx4 = MTOK * CDIM / 4;
    const int nq4 = 3 * CDIM * CDIM / 4;
    const int np4 = CDIM * CDIM / 4;

    conv_f16<<<(nx4 + 255) / 256, 256>>>(x, 0, nx4);
    conv_f16<<<(nq4 + 255) / 256, 256>>>(Wqkv, 1, nq4);
    conv_f16<<<(np4 + 255) / 256, 256>>>(Wproj, 2, np4);

    // QKV projection (fp16); epilogue: q fp16-split, k/v fp16
    gemm_tc<0><<<dim3(3 * CDIM / 128, MTOK / 128), 256, GSMEM>>>(nullptr, nullptr);

    // Flash attention (2-product asymmetric fp16); epilogue emits g_of fp16
    attn_flash<<<dim3(BPDIM * NHEAD, SEQ / 64), 256, ATTN_SMEM>>>();

    // Output projection (fp16) + bias -> d_out
    gemm_tc<1><<<dim3(CDIM / 128, MTOK / 128), 256, GSMEM>>>(out, bproj);
}

// round 9
// speedup vs baseline: 7.6878x; 1.0838x over previous
#include <cuda_runtime.h>
#include <cuda_bf16.h>
#include <cuda_fp16.h>
#include <math.h>
#include <stdint.h>

// Problem dims
#define SEQ    512
#define NHEAD  12
#define DHEAD  64
#define CDIM   768
#define BPDIM  32              // B*P = 8*4
#define MTOK   (BPDIM * SEQ)   // 16384 tokens
#define QSCALE 0.125f          // 64^-0.5

// ---------------------------------------------------------------------------
// Device-global scratch (allocation-free per harness rules)
// ---------------------------------------------------------------------------
#define HELEMS ((size_t)BPDIM * NHEAD * SEQ * DHEAD)   // 12.58M

// attention operands: q fp16 two-term split (pre-scaled), k/v single fp16
__device__ __half g_qh[HELEMS];
__device__ __half g_ql[HELEMS];
__device__ __half g_kf[HELEMS];
__device__ __half g_vf[HELEMS];

// fp16 operands for the two projection GEMMs
__device__ __half g_xf[(size_t)MTOK * CDIM];
__device__ __half g_of[(size_t)MTOK * CDIM];
__device__ __half g_wqf[(size_t)3 * CDIM * CDIM];
__device__ __half g_wpf[(size_t)CDIM * CDIM];

// ---------------------------------------------------------------------------
// Base-ISA tensor helpers (mma.sync + ldmatrix + cp.async — sm_103 base target)
// ---------------------------------------------------------------------------
__device__ __forceinline__ uint32_t smem_u32(const void* p) {
    uint32_t a;
    asm("{ .reg .u64 t; cvta.to.shared.u64 t, %1; cvt.u32.u64 %0, t; }"
        : "=r"(a) : "l"(p));
    return a;
}

__device__ __forceinline__ void ldmx4(uint32_t* r, uint32_t addr) {
    asm volatile("ldmatrix.sync.aligned.m8n8.x4.shared.b16 {%0,%1,%2,%3}, [%4];"
                 : "=r"(r[0]), "=r"(r[1]), "=r"(r[2]), "=r"(r[3]) : "r"(addr));
}
__device__ __forceinline__ void ldmx4t(uint32_t* r, uint32_t addr) {
    asm volatile("ldmatrix.sync.aligned.m8n8.x4.trans.shared.b16 {%0,%1,%2,%3}, [%4];"
                 : "=r"(r[0]), "=r"(r[1]), "=r"(r[2]), "=r"(r[3]) : "r"(addr));
}

__device__ __forceinline__ void mma_f16(float* c, const uint32_t* a,
                                        uint32_t b0, uint32_t b1) {
    asm volatile(
        "mma.sync.aligned.m16n8k16.row.col.f32.f16.f16.f32 "
        "{%0,%1,%2,%3}, {%4,%5,%6,%7}, {%8,%9}, {%0,%1,%2,%3};"
        : "+f"(c[0]), "+f"(c[1]), "+f"(c[2]), "+f"(c[3])
        : "r"(a[0]), "r"(a[1]), "r"(a[2]), "r"(a[3]), "r"(b0), "r"(b1));
}

__device__ __forceinline__ void cp16(uint32_t dst, const void* src) {
    asm volatile("cp.async.cg.shared.global [%0], [%1], 16;"
                 :: "r"(dst), "l"(src) : "memory");
}
#define CP_COMMIT() asm volatile("cp.async.commit_group;" ::: "memory")
#define CP_WAIT1()  asm volatile("cp.async.wait_group 1;" ::: "memory")
#define CP_WAIT0()  asm volatile("cp.async.wait_group 0;" ::: "memory")

// fp16 two-term split: hi = fp16(x), lo = fp16(x - hi)  (exact to ~2^-22)
__device__ __forceinline__ void split2h(float a0, float a1,
                                        uint32_t& hi, uint32_t& lo) {
    __half h0 = __float2half_rn(a0);
    __half h1 = __float2half_rn(a1);
    __half l0 = __float2half_rn(a0 - __half2float(h0));
    __half l1 = __float2half_rn(a1 - __half2float(h1));
    __half2 hh(h0, h1), ll(l0, l1);
    hi = *(uint32_t*)&hh;
    lo = *(uint32_t*)&ll;
}

// ---------------------------------------------------------------------------
// fp16 convert kernel.  sel: 0=x->g_xf  1=Wqkv->g_wqf  2=Wproj->g_wpf
// ---------------------------------------------------------------------------
__global__ void conv_f16(const float* __restrict__ in, int sel, int n4)
{
    __half* dst = (sel == 0) ? g_xf : (sel == 1) ? g_wqf : g_wpf;
    int i = blockIdx.x * blockDim.x + threadIdx.x;
    if (i >= n4) return;
    float4 v = ((const float4*)in)[i];
    ((__half2*)dst)[2 * i]     = __floats2half2_rn(v.x, v.y);
    ((__half2*)dst)[2 * i + 1] = __floats2half2_rn(v.z, v.w);
}

// ---------------------------------------------------------------------------
// Tensor-core GEMM (NT), single-product fp16, fp32 accumulate — unchanged.
// CTA 128x128, BK=64, 8 warps, 3-stage cp.async, XOR-swizzled 128B rows.
// ---------------------------------------------------------------------------
#define GT_B    16384
#define GSTG_B  (2 * GT_B)      // 32768
#define GSMEM   (3 * GSTG_B)    // 98304
#define NCHUNK  (CDIM / 64)     // 12

template <int MODE>
__global__ __launch_bounds__(256, 2)
void gemm_tc(float* __restrict__ Cout, const float* __restrict__ bias)
{
    extern __shared__ char smem[];
    const uint32_t sb = smem_u32(smem);
    const int tid = threadIdx.x;
    const int l   = tid & 31;
    const int warp = tid >> 5;
    const int wm = warp & 1;
    const int wn = warp >> 1;
    const int bn = blockIdx.x, bm = blockIdx.y;
    const int K = CDIM;

    const __half* srcs[2] = {
        ((MODE == 0) ? g_xf : g_of) + (size_t)(bm * 128) * K,
        ((MODE == 0) ? g_wqf : g_wpf) + (size_t)(bn * 128) * K };

    const int lrow  = l & 15;
    const int lhalf = l >> 4;

    float acc[4][4][4];
#pragma unroll
    for (int i = 0; i < 4; i++)
#pragma unroll
        for (int j = 0; j < 4; j++)
#pragma unroll
            for (int q = 0; q < 4; q++) acc[i][j][q] = 0.f;

#define LOAD_CHUNK(c, st)                                                      \
    do {                                                                       \
        _Pragma("unroll")                                                      \
        for (int j = 0; j < 8; j++) {                                          \
            const int i = tid + j * 256;                                       \
            const int t = i >> 10, r = (i >> 3) & 127, u = i & 7;              \
            const uint32_t dst = sb + (st) * GSTG_B + t * GT_B + r * 128       \
                               + ((u ^ (r & 7)) << 4);                         \
            cp16(dst, srcs[t] + (size_t)r * K + (c) * 64 + u * 8);             \
        }                                                                      \
        CP_COMMIT();                                                           \
    } while (0)

    LOAD_CHUNK(0, 0);
    LOAD_CHUNK(1, 1);

    for (int c = 0; c < NCHUNK; c++) {
        CP_WAIT1();
        __syncthreads();
        if (c + 2 < NCHUNK) {
            LOAD_CHUNK(c + 2, (c + 2) % 3);
        } else {
            CP_COMMIT();
        }

        const uint32_t stg = sb + (c % 3) * GSTG_B;
#pragma unroll
        for (int s = 0; s < 4; s++) {
            const int slot = s * 2 + lhalf;
            uint32_t bf[8];
#pragma unroll
            for (int np = 0; np < 2; np++) {
                const int R = wn * 32 + np * 16 + lrow;
                const uint32_t off = R * 128 + ((slot ^ (R & 7)) << 4);
                ldmx4(&bf[np * 4], stg + GT_B + off);
            }
#pragma unroll
            for (int mt = 0; mt < 4; mt++) {
                const int R = wm * 64 + mt * 16 + lrow;
                const uint32_t off = R * 128 + ((slot ^ (R & 7)) << 4);
                uint32_t af[4];
                ldmx4(af, stg + off);
#pragma unroll
                for (int nt = 0; nt < 4; nt++) {
                    const int np = nt >> 1, q = nt & 1;
                    mma_f16(acc[mt][nt], af, bf[np * 4 + q], bf[np * 4 + q + 2]);
                }
            }
        }
    }
#undef LOAD_CHUNK

#pragma unroll
    for (int mt = 0; mt < 4; mt++) {
#pragma unroll
        for (int nt = 0; nt < 4; nt++) {
            const int m0 = bm * 128 + wm * 64 + mt * 16 + (l >> 2);
            const int d  = bn * 128 + wn * 32 + nt * 8 + 2 * (l & 3);
#pragma unroll
            for (int half = 0; half < 2; half++) {
                const int m = m0 + half * 8;
                const float v0 = acc[mt][nt][half * 2 + 0];
                const float v1 = acc[mt][nt][half * 2 + 1];
                if (MODE == 0) {
                    const int bp = m >> 9;
                    const int n  = m & (SEQ - 1);
                    const int ss  = d / CDIM;
                    const int rem = d - ss * CDIM;
                    const int h   = rem >> 6;
                    const int hd  = rem & 63;
                    const size_t base = ((size_t)(bp * NHEAD + h) * SEQ + n) * DHEAD + hd;
                    if (ss == 0) {
                        uint32_t hi, lo;
                        split2h(v0 * QSCALE, v1 * QSCALE, hi, lo);
                        *(uint32_t*)(g_qh + base) = hi;
                        *(uint32_t*)(g_ql + base) = lo;
                    } else {
                        __half2 hv = __floats2half2_rn(v0, v1);
                        *(__half2*)(((ss == 1) ? g_kf : g_vf) + base) = hv;
                    }
                } else {
                    float2 bv = *(const float2*)(bias + d);
                    *(float2*)(Cout + (size_t)m * CDIM + d) =
                        make_float2(v0 + bv.x, v1 + bv.y);
                }
            }
        }
    }
}

// ---------------------------------------------------------------------------
// Flash attention v2: 128 queries/block, 8 warps each owning 16 FULL rows.
// No cross-warp softmax exchange, no O combine: row max/sum reduce within a
// lane quad; O normalizes in registers and stores straight to g_of.
// Per 64-key chunk: 2-product QK^T (fp16-split Q x fp16 K), online softmax,
// 2-product PV (fp16-split P x fp16 V). K/V cp.async double-buffered.
// SMEM: Q 2x18KB + KV 2x18KB = 72KB -> 2 CTA/SM.
// ---------------------------------------------------------------------------
#define AT_STRIDE 144
#define Q_TILE    (128 * AT_STRIDE)         // 18432
#define KV_TILE   (64 * AT_STRIDE)          // 9216
#define ASM_Q     0
#define ASM_KV    (2 * Q_TILE)              // 36864
#define ASM_STG   (2 * KV_TILE)             // 18432 per stage (K, V)
#define ATTN_SMEM (ASM_KV + 2 * ASM_STG)    // 73728

__global__ __launch_bounds__(256, 2)
void attn_flash()
{
    extern __shared__ char sm[];
    const uint32_t sb = smem_u32(sm);

    const int tid = threadIdx.x, l = tid & 31, w = tid >> 5;
    const int bph = blockIdx.x, qt = blockIdx.y;   // qt in 0..3 (128-query tiles)
    const size_t hoff = (size_t)bph * SEQ * DHEAD;
    const __half* qh = g_qh + hoff + (size_t)qt * 128 * DHEAD;
    const __half* ql = g_ql + hoff + (size_t)qt * 128 * DHEAD;
    const __half* asrc[2] = { g_kf + hoff, g_vf + hoff };

    const int lrow = l & 15;
    const int lcolb = (l >> 4) << 4;
    const int r0 = w * 16 + (l >> 2);   // warp-owned query row (and +8)

#define ALOAD(c, st)                                                           \
    do {                                                                       \
        _Pragma("unroll")                                                      \
        for (int j = 0; j < 4; j++) {                                          \
            const int i = tid + j * 256;                                       \
            const int t = i >> 9, r = (i >> 3) & 63, u = i & 7;                \
            cp16(sb + ASM_KV + (st) * ASM_STG + t * KV_TILE + r * AT_STRIDE    \
                     + u * 16,                                                 \
                 asrc[t] + (size_t)(c) * 64 * 64 + r * 64 + u * 8);            \
        }                                                                      \
        CP_COMMIT();                                                           \
    } while (0)

    ALOAD(0, 0);

    // Q tiles (h,l): 128 rows x 64 halves each, plain one-time stores
    for (int i = tid; i < 2048; i += 256) {
        const int t = i >> 10, r = (i >> 3) & 127, u = i & 7;
        const __half* src = (t == 0) ? qh : ql;
        *(uint4*)(sm + ASM_Q + t * Q_TILE + r * AT_STRIDE + u * 16) =
            *(const uint4*)(src + r * 64 + u * 8);
    }

    float accO[8][4];
#pragma unroll
    for (int i = 0; i < 8; i++)
#pragma unroll
        for (int q = 0; q < 4; q++) accO[i][q] = 0.f;
    float mrun0 = -1e30f, mrun1 = -1e30f;
    float lsum0 = 0.f, lsum1 = 0.f;

    for (int kc = 0; kc < 8; kc++) {
        if (kc < 7) { ALOAD(kc + 1, (kc + 1) & 1); CP_WAIT1(); }
        else        { CP_WAIT0(); }
        __syncthreads();

        const uint32_t stg = sb + ASM_KV + (kc & 1) * ASM_STG;

        // ---- QK^T: 16 queries x 64 keys, 2 products ----
        float accS[8][4];
#pragma unroll
        for (int i = 0; i < 8; i++)
#pragma unroll
            for (int q = 0; q < 4; q++) accS[i][q] = 0.f;
#pragma unroll
        for (int ks = 0; ks < 4; ks++) {
            uint32_t qfh[4], qfl[4];
            const uint32_t qro = (w * 16 + lrow) * AT_STRIDE + ks * 32 + lcolb;
            ldmx4(qfh, sb + ASM_Q + qro);
            ldmx4(qfl, sb + ASM_Q + Q_TILE + qro);
            uint32_t kb[16];
#pragma unroll
            for (int np = 0; np < 4; np++) {
                const uint32_t off = (np * 16 + lrow) * AT_STRIDE + ks * 32 + lcolb;
                ldmx4(&kb[np * 4], stg + off);
            }
#pragma unroll
            for (int nt = 0; nt < 8; nt++) {
                const int np = nt >> 1, q = nt & 1;
                mma_f16(accS[nt], qfh, kb[np * 4 + q], kb[np * 4 + q + 2]);
                mma_f16(accS[nt], qfl, kb[np * 4 + q], kb[np * 4 + q + 2]);
            }
        }

        // ---- online softmax: row max within lane quad (no SMEM, no sync) ----
        float ml0 = -1e30f, ml1 = -1e30f;
#pragma unroll
        for (int nt = 0; nt < 8; nt++) {
            ml0 = fmaxf(ml0, fmaxf(accS[nt][0], accS[nt][1]));
            ml1 = fmaxf(ml1, fmaxf(accS[nt][2], accS[nt][3]));
        }
        ml0 = fmaxf(ml0, __shfl_xor_sync(0xffffffffu, ml0, 1));
        ml0 = fmaxf(ml0, __shfl_xor_sync(0xffffffffu, ml0, 2));
        ml1 = fmaxf(ml1, __shfl_xor_sync(0xffffffffu, ml1, 1));
        ml1 = fmaxf(ml1, __shfl_xor_sync(0xffffffffu, ml1, 2));
        const float mn0 = fmaxf(mrun0, ml0), mn1 = fmaxf(mrun1, ml1);
        const float sc0 = __expf(mrun0 - mn0), sc1 = __expf(mrun1 - mn1);
        mrun0 = mn0; mrun1 = mn1;
        lsum0 *= sc0; lsum1 *= sc1;
#pragma unroll
        for (int nt = 0; nt < 8; nt++) {
            accO[nt][0] *= sc0; accO[nt][1] *= sc0;
            accO[nt][2] *= sc1; accO[nt][3] *= sc1;
        }

        // ---- P=exp -> fp16-split A-frags -> PV, per 16-key group ----
        float ps0 = 0.f, ps1 = 0.f;
#pragma unroll
        for (int kb2 = 0; kb2 < 4; kb2++) {
            const float p00 = __expf(accS[2 * kb2][0] - mn0);
            const float p01 = __expf(accS[2 * kb2][1] - mn0);
            const float p10 = __expf(accS[2 * kb2][2] - mn1);
            const float p11 = __expf(accS[2 * kb2][3] - mn1);
            const float p20 = __expf(accS[2 * kb2 + 1][0] - mn0);
            const float p21 = __expf(accS[2 * kb2 + 1][1] - mn0);
            const float p30 = __expf(accS[2 * kb2 + 1][2] - mn1);
            const float p31 = __expf(accS[2 * kb2 + 1][3] - mn1);
            ps0 += p00 + p01 + p20 + p21;
            ps1 += p10 + p11 + p30 + p31;
            uint32_t Ph[4], Pl[4];
            split2h(p00, p01, Ph[0], Pl[0]);
            split2h(p10, p11, Ph[1], Pl[1]);
            split2h(p20, p21, Ph[2], Pl[2]);
            split2h(p30, p31, Ph[3], Pl[3]);
#pragma unroll
            for (int np = 0; np < 4; np++) {
                uint32_t vb[4];
                const uint32_t ad =
                    (kb2 * 16 + (l & 7) + (((l >> 3) & 1) << 3)) * AT_STRIDE
                    + (np * 16 + ((l >> 4) << 3)) * 2;
                ldmx4t(vb, stg + KV_TILE + ad);
#pragma unroll
                for (int q = 0; q < 2; q++) {
                    const int nt = np * 2 + q;
                    mma_f16(accO[nt], Ph, vb[2 * q], vb[2 * q + 1]);
                    mma_f16(accO[nt], Pl, vb[2 * q], vb[2 * q + 1]);
                }
            }
        }
        ps0 += __shfl_xor_sync(0xffffffffu, ps0, 1);
        ps0 += __shfl_xor_sync(0xffffffffu, ps0, 2);
        ps1 += __shfl_xor_sync(0xffffffffu, ps1, 1);
        ps1 += __shfl_xor_sync(0xffffffffu, ps1, 2);
        lsum0 += ps0; lsum1 += ps1;

        __syncthreads();   // stage reuse fence
    }
#undef ALOAD

    // ---- epilogue: normalize in registers, store fp16 direct to global ----
    const int h  = bph % NHEAD;
    const int bp = bph / NHEAD;
    const float inv0 = 1.0f / lsum0;
    const float inv1 = 1.0f / lsum1;
    const size_t row0 = ((size_t)bp * SEQ + qt * 128 + r0) * CDIM + h * DHEAD;
    const size_t row1 = row0 + (size_t)8 * CDIM;
#pragma unroll
    for (int nt = 0; nt < 8; nt++) {
        const int col = nt * 8 + 2 * (l & 3);
        *(__half2*)(g_of + row0 + col) =
            __floats2half2_rn(accO[nt][0] * inv0, accO[nt][1] * inv0);
        *(__half2*)(g_of + row1 + col) =
            __floats2half2_rn(accO[nt][2] * inv1, accO[nt][3] * inv1);
    }
}

// ---------------------------------------------------------------------------
extern "C" void kernel_launch(void* const* d_in, const int* in_sizes, int n_in,
                              void* d_out, int out_size)
{
    const float* x     = (const float*)d_in[0];  // (8,4,512,768)
    const float* Wqkv  = (const float*)d_in[1];  // (2304,768)
    const float* Wproj = (const float*)d_in[2];  // (768,768)
    const float* bproj = (const float*)d_in[3];  // (768,)
    float* out = (float*)d_out;

    cudaFuncSetAttribute(gemm_tc<0>, cudaFuncAttributeMaxDynamicSharedMemorySize, GSMEM);
    cudaFuncSetAttribute(gemm_tc<1>, cudaFuncAttributeMaxDynamicSharedMemorySize, GSMEM);
    cudaFuncSetAttribute(attn_flash, cudaFuncAttributeMaxDynamicSharedMemorySize, ATTN_SMEM);

    const int nx4 = MTOK * CDIM / 4;
    const int nq4 = 3 * CDIM * CDIM / 4;
    const int np4 = CDIM * CDIM / 4;

    conv_f16<<<(nx4 + 255) / 256, 256>>>(x, 0, nx4);
    conv_f16<<<(nq4 + 255) / 256, 256>>>(Wqkv, 1, nq4);
    conv_f16<<<(np4 + 255) / 256, 256>>>(Wproj, 2, np4);

    // QKV projection (fp16); epilogue: q fp16-split, k/v fp16
    gemm_tc<0><<<dim3(3 * CDIM / 128, MTOK / 128), 256, GSMEM>>>(nullptr, nullptr);

    // Flash attention v2: 128 queries/block, warp-owned rows
    attn_flash<<<dim3(BPDIM * NHEAD, SEQ / 128), 256, ATTN_SMEM>>>();

    // Output projection (fp16) + bias -> d_out
    gemm_tc<1><<<dim3(CDIM / 128, MTOK / 128), 256, GSMEM>>>(out, bproj);
}

// round 10
// speedup vs baseline: 8.9549x; 1.1648x over previous
#include <cuda_runtime.h>
#include <cuda_bf16.h>
#include <cuda_fp16.h>
#include <math.h>
#include <stdint.h>

// Problem dims
#define SEQ    512
#define NHEAD  12
#define DHEAD  64
#define CDIM   768
#define BPDIM  32              // B*P = 8*4
#define MTOK   (BPDIM * SEQ)   // 16384 tokens
#define QSCALE 0.125f          // 64^-0.5

// ---------------------------------------------------------------------------
// Device-global scratch (allocation-free per harness rules)
// ---------------------------------------------------------------------------
#define HELEMS ((size_t)BPDIM * NHEAD * SEQ * DHEAD)   // 12.58M

// attention operands: single fp16 (q pre-scaled)
__device__ __half g_qf[HELEMS];
__device__ __half g_kf[HELEMS];
__device__ __half g_vf[HELEMS];

// fp16 operands for the two projection GEMMs
__device__ __half g_xf[(size_t)MTOK * CDIM];
__device__ __half g_of[(size_t)MTOK * CDIM];
__device__ __half g_wqf[(size_t)3 * CDIM * CDIM];
__device__ __half g_wpf[(size_t)CDIM * CDIM];

// ---------------------------------------------------------------------------
// Base-ISA tensor helpers (mma.sync + ldmatrix + cp.async — sm_103 base target)
// ---------------------------------------------------------------------------
__device__ __forceinline__ uint32_t smem_u32(const void* p) {
    uint32_t a;
    asm("{ .reg .u64 t; cvta.to.shared.u64 t, %1; cvt.u32.u64 %0, t; }"
        : "=r"(a) : "l"(p));
    return a;
}

__device__ __forceinline__ void ldmx4(uint32_t* r, uint32_t addr) {
    asm volatile("ldmatrix.sync.aligned.m8n8.x4.shared.b16 {%0,%1,%2,%3}, [%4];"
                 : "=r"(r[0]), "=r"(r[1]), "=r"(r[2]), "=r"(r[3]) : "r"(addr));
}
__device__ __forceinline__ void ldmx4t(uint32_t* r, uint32_t addr) {
    asm volatile("ldmatrix.sync.aligned.m8n8.x4.trans.shared.b16 {%0,%1,%2,%3}, [%4];"
                 : "=r"(r[0]), "=r"(r[1]), "=r"(r[2]), "=r"(r[3]) : "r"(addr));
}

__device__ __forceinline__ void mma_f16(float* c, const uint32_t* a,
                                        uint32_t b0, uint32_t b1) {
    asm volatile(
        "mma.sync.aligned.m16n8k16.row.col.f32.f16.f16.f32 "
        "{%0,%1,%2,%3}, {%4,%5,%6,%7}, {%8,%9}, {%0,%1,%2,%3};"
        : "+f"(c[0]), "+f"(c[1]), "+f"(c[2]), "+f"(c[3])
        : "r"(a[0]), "r"(a[1]), "r"(a[2]), "r"(a[3]), "r"(b0), "r"(b1));
}

__device__ __forceinline__ void cp16(uint32_t dst, const void* src) {
    asm volatile("cp.async.cg.shared.global [%0], [%1], 16;"
                 :: "r"(dst), "l"(src) : "memory");
}
#define CP_COMMIT() asm volatile("cp.async.commit_group;" ::: "memory")
#define CP_WAIT1()  asm volatile("cp.async.wait_group 1;" ::: "memory")
#define CP_WAIT0()  asm volatile("cp.async.wait_group 0;" ::: "memory")

// ---------------------------------------------------------------------------
// Merged fp16 convert kernel: x -> g_xf, Wqkv -> g_wqf, Wproj -> g_wpf
// ---------------------------------------------------------------------------
#define NX4 (MTOK * CDIM / 4)              // 3145728
#define NQ4 (3 * CDIM * CDIM / 4)          // 442368
#define NP4 (CDIM * CDIM / 4)              // 147456
#define NALL4 (NX4 + NQ4 + NP4)

__global__ void conv_all(const float* __restrict__ x,
                         const float* __restrict__ wq,
                         const float* __restrict__ wp)
{
    int i = blockIdx.x * blockDim.x + threadIdx.x;
    const float* src;
    __half* dst;
    int j;
    if (i < NX4)            { src = x;  dst = g_xf;  j = i; }
    else if (i < NX4 + NQ4) { src = wq; dst = g_wqf; j = i - NX4; }
    else if (i < NALL4)     { src = wp; dst = g_wpf; j = i - NX4 - NQ4; }
    else return;
    float4 v = ((const float4*)src)[j];
    ((__half2*)dst)[2 * j]     = __floats2half2_rn(v.x, v.y);
    ((__half2*)dst)[2 * j + 1] = __floats2half2_rn(v.z, v.w);
}

// ---------------------------------------------------------------------------
// Tensor-core GEMM (NT), single-product fp16, fp32 accumulate.
// CTA 128x128, BK=64, 8 warps, 3-stage cp.async, XOR-swizzled 128B rows.
// MODE 0: A=g_xf, B=g_wqf; epilogue: q (scaled) / k / v single fp16.
// MODE 1: A=g_of, B=g_wpf; +bias -> d_out (fp32).
// ---------------------------------------------------------------------------
#define GT_B    16384
#define GSTG_B  (2 * GT_B)      // 32768
#define GSMEM   (3 * GSTG_B)    // 98304
#define NCHUNK  (CDIM / 64)     // 12

template <int MODE>
__global__ __launch_bounds__(256, 2)
void gemm_tc(float* __restrict__ Cout, const float* __restrict__ bias)
{
    extern __shared__ char smem[];
    const uint32_t sb = smem_u32(smem);
    const int tid = threadIdx.x;
    const int l   = tid & 31;
    const int warp = tid >> 5;
    const int wm = warp & 1;
    const int wn = warp >> 1;
    const int bn = blockIdx.x, bm = blockIdx.y;
    const int K = CDIM;

    const __half* srcs[2] = {
        ((MODE == 0) ? g_xf : g_of) + (size_t)(bm * 128) * K,
        ((MODE == 0) ? g_wqf : g_wpf) + (size_t)(bn * 128) * K };

    const int lrow  = l & 15;
    const int lhalf = l >> 4;

    float acc[4][4][4];
#pragma unroll
    for (int i = 0; i < 4; i++)
#pragma unroll
        for (int j = 0; j < 4; j++)
#pragma unroll
            for (int q = 0; q < 4; q++) acc[i][j][q] = 0.f;

#define LOAD_CHUNK(c, st)                                                      \
    do {                                                                       \
        _Pragma("unroll")                                                      \
        for (int j = 0; j < 8; j++) {                                          \
            const int i = tid + j * 256;                                       \
            const int t = i >> 10, r = (i >> 3) & 127, u = i & 7;              \
            const uint32_t dst = sb + (st) * GSTG_B + t * GT_B + r * 128       \
                               + ((u ^ (r & 7)) << 4);                         \
            cp16(dst, srcs[t] + (size_t)r * K + (c) * 64 + u * 8);             \
        }                                                                      \
        CP_COMMIT();                                                           \
    } while (0)

    LOAD_CHUNK(0, 0);
    LOAD_CHUNK(1, 1);

    for (int c = 0; c < NCHUNK; c++) {
        CP_WAIT1();
        __syncthreads();
        if (c + 2 < NCHUNK) {
            LOAD_CHUNK(c + 2, (c + 2) % 3);
        } else {
            CP_COMMIT();
        }

        const uint32_t stg = sb + (c % 3) * GSTG_B;
#pragma unroll
        for (int s = 0; s < 4; s++) {
            const int slot = s * 2 + lhalf;
            uint32_t bf[8];
#pragma unroll
            for (int np = 0; np < 2; np++) {
                const int R = wn * 32 + np * 16 + lrow;
                const uint32_t off = R * 128 + ((slot ^ (R & 7)) << 4);
                ldmx4(&bf[np * 4], stg + GT_B + off);
            }
#pragma unroll
            for (int mt = 0; mt < 4; mt++) {
                const int R = wm * 64 + mt * 16 + lrow;
                const uint32_t off = R * 128 + ((slot ^ (R & 7)) << 4);
                uint32_t af[4];
                ldmx4(af, stg + off);
#pragma unroll
                for (int nt = 0; nt < 4; nt++) {
                    const int np = nt >> 1, q = nt & 1;
                    mma_f16(acc[mt][nt], af, bf[np * 4 + q], bf[np * 4 + q + 2]);
                }
            }
        }
    }
#undef LOAD_CHUNK

#pragma unroll
    for (int mt = 0; mt < 4; mt++) {
#pragma unroll
        for (int nt = 0; nt < 4; nt++) {
            const int m0 = bm * 128 + wm * 64 + mt * 16 + (l >> 2);
            const int d  = bn * 128 + wn * 32 + nt * 8 + 2 * (l & 3);
#pragma unroll
            for (int half = 0; half < 2; half++) {
                const int m = m0 + half * 8;
                const float v0 = acc[mt][nt][half * 2 + 0];
                const float v1 = acc[mt][nt][half * 2 + 1];
                if (MODE == 0) {
                    const int bp = m >> 9;
                    const int n  = m & (SEQ - 1);
                    const int ss  = d / CDIM;
                    const int rem = d - ss * CDIM;
                    const int h   = rem >> 6;
                    const int hd  = rem & 63;
                    const size_t base = ((size_t)(bp * NHEAD + h) * SEQ + n) * DHEAD + hd;
                    const float sc = (ss == 0) ? QSCALE : 1.0f;
                    __half* dst = (ss == 0) ? g_qf : (ss == 1) ? g_kf : g_vf;
                    *(__half2*)(dst + base) = __floats2half2_rn(v0 * sc, v1 * sc);
                } else {
                    float2 bv = *(const float2*)(bias + d);
                    *(float2*)(Cout + (size_t)m * CDIM + d) =
                        make_float2(v0 + bv.x, v1 + bv.y);
                }
            }
        }
    }
}

// ---------------------------------------------------------------------------
// Flash attention v3: 128 queries/block, 8 warps each owning 16 FULL rows.
// Single-product fp16 QK^T and PV (fp32 accumulate). Row max/sum within a
// lane quad (no cross-warp exchange); O normalized in registers, stored
// straight to g_of. K/V cp.async double-buffered.
// SMEM: Q 18KB + KV 2x18KB = 54KB -> 2 CTA/SM.
// ---------------------------------------------------------------------------
#define AT_STRIDE 144
#define Q_TILE    (128 * AT_STRIDE)         // 18432
#define KV_TILE   (64 * AT_STRIDE)          // 9216
#define ASM_KV    Q_TILE                    // 18432
#define ASM_STG   (2 * KV_TILE)             // 18432 per stage (K, V)
#define ATTN_SMEM (ASM_KV + 2 * ASM_STG)    // 55296

__global__ __launch_bounds__(256, 2)
void attn_flash()
{
    extern __shared__ char sm[];
    const uint32_t sb = smem_u32(sm);

    const int tid = threadIdx.x, l = tid & 31, w = tid >> 5;
    const int bph = blockIdx.x, qt = blockIdx.y;   // qt in 0..3 (128-query tiles)
    const size_t hoff = (size_t)bph * SEQ * DHEAD;
    const __half* qf = g_qf + hoff + (size_t)qt * 128 * DHEAD;
    const __half* asrc[2] = { g_kf + hoff, g_vf + hoff };

    const int lrow = l & 15;
    const int lcolb = (l >> 4) << 4;
    const int r0 = w * 16 + (l >> 2);   // warp-owned query row (and +8)

#define ALOAD(c, st)                                                           \
    do {                                                                       \
        _Pragma("unroll")                                                      \
        for (int j = 0; j < 4; j++) {                                          \
            const int i = tid + j * 256;                                       \
            const int t = i >> 9, r = (i >> 3) & 63, u = i & 7;                \
            cp16(sb + ASM_KV + (st) * ASM_STG + t * KV_TILE + r * AT_STRIDE    \
                     + u * 16,                                                 \
                 asrc[t] + (size_t)(c) * 64 * 64 + r * 64 + u * 8);            \
        }                                                                      \
        CP_COMMIT();                                                           \
    } while (0)

    ALOAD(0, 0);

    // Q tile: 128 rows x 64 halves, one-time plain stores
    for (int i = tid; i < 1024; i += 256) {
        const int r = i >> 3, u = i & 7;
        *(uint4*)(sm + r * AT_STRIDE + u * 16) = *(const uint4*)(qf + r * 64 + u * 8);
    }

    float accO[8][4];
#pragma unroll
    for (int i = 0; i < 8; i++)
#pragma unroll
        for (int q = 0; q < 4; q++) accO[i][q] = 0.f;
    float mrun0 = -1e30f, mrun1 = -1e30f;
    float lsum0 = 0.f, lsum1 = 0.f;

    for (int kc = 0; kc < 8; kc++) {
        if (kc < 7) { ALOAD(kc + 1, (kc + 1) & 1); CP_WAIT1(); }
        else        { CP_WAIT0(); }
        __syncthreads();

        const uint32_t stg = sb + ASM_KV + (kc & 1) * ASM_STG;

        // ---- QK^T: 16 queries x 64 keys, single product ----
        float accS[8][4];
#pragma unroll
        for (int i = 0; i < 8; i++)
#pragma unroll
            for (int q = 0; q < 4; q++) accS[i][q] = 0.f;
#pragma unroll
        for (int ks = 0; ks < 4; ks++) {
            uint32_t qfr[4];
            const uint32_t qro = (w * 16 + lrow) * AT_STRIDE + ks * 32 + lcolb;
            ldmx4(qfr, sb + qro);
            uint32_t kb[16];
#pragma unroll
            for (int np = 0; np < 4; np++) {
                const uint32_t off = (np * 16 + lrow) * AT_STRIDE + ks * 32 + lcolb;
                ldmx4(&kb[np * 4], stg + off);
            }
#pragma unroll
            for (int nt = 0; nt < 8; nt++) {
                const int np = nt >> 1, q = nt & 1;
                mma_f16(accS[nt], qfr, kb[np * 4 + q], kb[np * 4 + q + 2]);
            }
        }

        // ---- online softmax: row max within lane quad ----
        float ml0 = -1e30f, ml1 = -1e30f;
#pragma unroll
        for (int nt = 0; nt < 8; nt++) {
            ml0 = fmaxf(ml0, fmaxf(accS[nt][0], accS[nt][1]));
            ml1 = fmaxf(ml1, fmaxf(accS[nt][2], accS[nt][3]));
        }
        ml0 = fmaxf(ml0, __shfl_xor_sync(0xffffffffu, ml0, 1));
        ml0 = fmaxf(ml0, __shfl_xor_sync(0xffffffffu, ml0, 2));
        ml1 = fmaxf(ml1, __shfl_xor_sync(0xffffffffu, ml1, 1));
        ml1 = fmaxf(ml1, __shfl_xor_sync(0xffffffffu, ml1, 2));
        const float mn0 = fmaxf(mrun0, ml0), mn1 = fmaxf(mrun1, ml1);
        const float sc0 = __expf(mrun0 - mn0), sc1 = __expf(mrun1 - mn1);
        mrun0 = mn0; mrun1 = mn1;
        lsum0 *= sc0; lsum1 *= sc1;
#pragma unroll
        for (int nt = 0; nt < 8; nt++) {
            accO[nt][0] *= sc0; accO[nt][1] *= sc0;
            accO[nt][2] *= sc1; accO[nt][3] *= sc1;
        }

        // ---- P=exp -> fp16 A-frags -> PV, per 16-key group ----
        float ps0 = 0.f, ps1 = 0.f;
#pragma unroll
        for (int kb2 = 0; kb2 < 4; kb2++) {
            const float p00 = __expf(accS[2 * kb2][0] - mn0);
            const float p01 = __expf(accS[2 * kb2][1] - mn0);
            const float p10 = __expf(accS[2 * kb2][2] - mn1);
            const float p11 = __expf(accS[2 * kb2][3] - mn1);
            const float p20 = __expf(accS[2 * kb2 + 1][0] - mn0);
            const float p21 = __expf(accS[2 * kb2 + 1][1] - mn0);
            const float p30 = __expf(accS[2 * kb2 + 1][2] - mn1);
            const float p31 = __expf(accS[2 * kb2 + 1][3] - mn1);
            ps0 += p00 + p01 + p20 + p21;
            ps1 += p10 + p11 + p30 + p31;
            uint32_t Pf[4];
            __half2 t0 = __floats2half2_rn(p00, p01); Pf[0] = *(uint32_t*)&t0;
            __half2 t1 = __floats2half2_rn(p10, p11); Pf[1] = *(uint32_t*)&t1;
            __half2 t2 = __floats2half2_rn(p20, p21); Pf[2] = *(uint32_t*)&t2;
            __half2 t3 = __floats2half2_rn(p30, p31); Pf[3] = *(uint32_t*)&t3;
#pragma unroll
            for (int np = 0; np < 4; np++) {
                uint32_t vb[4];
                const uint32_t ad =
                    (kb2 * 16 + (l & 7) + (((l >> 3) & 1) << 3)) * AT_STRIDE
                    + (np * 16 + ((l >> 4) << 3)) * 2;
                ldmx4t(vb, stg + KV_TILE + ad);
#pragma unroll
                for (int q = 0; q < 2; q++)
                    mma_f16(accO[np * 2 + q], Pf, vb[2 * q], vb[2 * q + 1]);
            }
        }
        ps0 += __shfl_xor_sync(0xffffffffu, ps0, 1);
        ps0 += __shfl_xor_sync(0xffffffffu, ps0, 2);
        ps1 += __shfl_xor_sync(0xffffffffu, ps1, 1);
        ps1 += __shfl_xor_sync(0xffffffffu, ps1, 2);
        lsum0 += ps0; lsum1 += ps1;

        __syncthreads();   // stage reuse fence
    }
#undef ALOAD

    // ---- epilogue: normalize in registers, store fp16 direct to global ----
    const int h  = bph % NHEAD;
    const int bp = bph / NHEAD;
    const float inv0 = 1.0f / lsum0;
    const float inv1 = 1.0f / lsum1;
    const size_t row0 = ((size_t)bp * SEQ + qt * 128 + r0) * CDIM + h * DHEAD;
    const size_t row1 = row0 + (size_t)8 * CDIM;
#pragma unroll
    for (int nt = 0; nt < 8; nt++) {
        const int col = nt * 8 + 2 * (l & 3);
        *(__half2*)(g_of + row0 + col) =
            __floats2half2_rn(accO[nt][0] * inv0, accO[nt][1] * inv0);
        *(__half2*)(g_of + row1 + col) =
            __floats2half2_rn(accO[nt][2] * inv1, accO[nt][3] * inv1);
    }
}

// ---------------------------------------------------------------------------
extern "C" void kernel_launch(void* const* d_in, const int* in_sizes, int n_in,
                              void* d_out, int out_size)
{
    const float* x     = (const float*)d_in[0];  // (8,4,512,768)
    const float* Wqkv  = (const float*)d_in[1];  // (2304,768)
    const float* Wproj = (const float*)d_in[2];  // (768,768)
    const float* bproj = (const float*)d_in[3];  // (768,)
    float* out = (float*)d_out;

    cudaFuncSetAttribute(gemm_tc<0>, cudaFuncAttributeMaxDynamicSharedMemorySize, GSMEM);
    cudaFuncSetAttribute(gemm_tc<1>, cudaFuncAttributeMaxDynamicSharedMemorySize, GSMEM);
    cudaFuncSetAttribute(attn_flash, cudaFuncAttributeMaxDynamicSharedMemorySize, ATTN_SMEM);

    // All three fp32->fp16 conversions in one launch
    conv_all<<<(NALL4 + 255) / 256, 256>>>(x, Wqkv, Wproj);

    // QKV projection (fp16); epilogue: q (scaled) / k / v single fp16
    gemm_tc<0><<<dim3(3 * CDIM / 128, MTOK / 128), 256, GSMEM>>>(nullptr, nullptr);

    // Flash attention v3: single-product fp16, 128 queries/block
    attn_flash<<<dim3(BPDIM * NHEAD, SEQ / 128), 256, ATTN_SMEM>>>();

    // Output projection (fp16) + bias -> d_out
    gemm_tc<1><<<dim3(CDIM / 128, MTOK / 128), 256, GSMEM>>>(out, bproj);
}